// round 1
// baseline (speedup 1.0000x reference)
#include <cuda_runtime.h>
#include <cuda_bf16.h>
#include <cstdint>

#define BB 16
#define HH 48
#define WWD 48
#define CC 128
#define GG 4
#define NHH 8
#define SSW 8
#define LL (HH*WWD)          // 2304
#define HD (CC/NHH)          // 16
#define NWIN (WWD/SSW)       // 6
#define SEQ (HH*SSW)         // 384

// scratch (no allocations allowed)
__device__ float g_pooled[BB*9*CC];
__device__ float g_w[BB*CC*9];
__device__ float g_bias[BB*CC];

typedef unsigned long long ull;

__device__ __forceinline__ ull ffma2(ull a, ull b, ull c){
  ull d; asm("fma.rn.f32x2 %0,%1,%2,%3;" : "=l"(d) : "l"(a), "l"(b), "l"(c)); return d;
}
__device__ __forceinline__ ull pack2(float lo, float hi){
  ull r; asm("mov.b64 %0,{%1,%2};" : "=l"(r) : "f"(lo), "f"(hi)); return r;
}
__device__ __forceinline__ float2 unpack2(ull a){
  float2 r; asm("mov.b64 {%0,%1},%2;" : "=f"(r.x), "=f"(r.y) : "l"(a)); return r;
}
__device__ __forceinline__ float ex2f(float x){
  float r; asm("ex2.approx.ftz.f32 %0,%1;" : "=f"(r) : "f"(x)); return r;
}

// ---------------------------------------------------------------------------
// Kernel 1: adaptive avg pool to 3x3 (uniform 16x16 block means)
// grid (9 bins, 16 batches), 256 threads
// ---------------------------------------------------------------------------
__global__ void pool_kernel(const float* __restrict__ v){
  const int bin = blockIdx.x, b = blockIdx.y;
  const int ky = bin / 3, kx = bin - ky*3;
  const int tid = threadIdx.x;
  const int c = tid & 127, part = tid >> 7;
  const float* vb = v + (size_t)b*LL*CC;
  float s = 0.f;
  const int h0 = ky*16 + part*8;
  for (int hh = 0; hh < 8; hh++){
    const float* row = vb + (size_t)((h0+hh)*WWD + kx*16)*CC + c;
    #pragma unroll
    for (int ww = 0; ww < 16; ww++) s += row[ww*CC];
  }
  __shared__ float sred[128];
  if (part) sred[c] = s;
  __syncthreads();
  if (!part) g_pooled[(b*9 + bin)*CC + c] = (s + sred[c]) * (1.f/256.f);
}

// ---------------------------------------------------------------------------
// Kernel 2: proj1 -> BN -> GELU -> proj2 -> softmax over G -> dyn w / bias
// grid 16 (batch), 256 threads, dynamic smem
// ---------------------------------------------------------------------------
__global__ void proj_kernel(const float* __restrict__ p1w, const float* __restrict__ p1b,
                            const float* __restrict__ bng, const float* __restrict__ bnb,
                            const float* __restrict__ bnm, const float* __restrict__ bnv,
                            const float* __restrict__ p2w, const float* __restrict__ p2b,
                            const float* __restrict__ dynw, const float* __restrict__ dynb){
  const int b = blockIdx.x, tid = threadIdx.x;
  extern __shared__ float ps[];
  float* pp  = ps;             // 10*128  (pos 9 = global mean)
  float* act = pp + 1280;      // 10*32
  float* p1t = act + 320;      // [c][o]  128*32
  float* w2t = p1t + 4096;     // [o][oc] 32*512

  for (int i = tid; i < 9*CC; i += 256) pp[i] = g_pooled[b*9*CC + i];
  for (int i = tid; i < 4096; i += 256){ int o = i >> 7, c = i & 127; p1t[c*32+o] = p1w[i]; }
  for (int i = tid; i < 16384; i += 256){ int oc = i >> 5, o = i & 31; w2t[o*512+oc] = p2w[i]; }
  __syncthreads();
  if (tid < 128){
    float s = 0.f;
    #pragma unroll
    for (int q = 0; q < 9; q++) s += pp[q*CC + tid];
    pp[9*CC + tid] = s * (1.f/9.f);
  }
  __syncthreads();

  // stage A: 10 positions x 32 outputs
  for (int t = tid; t < 320; t += 256){
    int pos = t >> 5, o = t & 31;
    float s = p1b[o];
    const float* prow = pp + pos*CC;
    #pragma unroll 8
    for (int cc = 0; cc < CC; cc++) s += p1t[cc*32+o] * prow[cc];
    float inv = rsqrtf(bnv[o] + 1e-5f);
    s = (s - bnm[o]) * (inv * bng[o]) + bnb[o];
    s = 0.5f * s * (1.f + erff(s * 0.70710678118654752f));
    act[pos*32+o] = s;
  }
  __syncthreads();

  // stage B: 10 positions x 128 channels: 4 group scores -> softmax -> combine
  for (int t = tid; t < 1280; t += 256){
    int pos = t >> 7, c = t & 127;
    float y[4];
    #pragma unroll
    for (int g = 0; g < 4; g++){
      int oc = g*CC + c;
      float s = p2b[oc];
      #pragma unroll
      for (int o = 0; o < 32; o++) s += w2t[o*512+oc] * act[pos*32+o];
      y[g] = s;
    }
    float m = fmaxf(fmaxf(y[0],y[1]), fmaxf(y[2],y[3]));
    float e0 = expf(y[0]-m), e1 = expf(y[1]-m), e2 = expf(y[2]-m), e3 = expf(y[3]-m);
    float rs = 1.f / (e0+e1+e2+e3);
    if (pos < 9){
      float wv = e0*dynw[(0*CC+c)*9+pos] + e1*dynw[(1*CC+c)*9+pos]
               + e2*dynw[(2*CC+c)*9+pos] + e3*dynw[(3*CC+c)*9+pos];
      g_w[(b*CC + c)*9 + pos] = wv * rs;
    } else {
      float bv = e0*dynb[0*CC+c] + e1*dynb[1*CC+c] + e2*dynb[2*CC+c] + e3*dynb[3*CC+c];
      g_bias[b*CC + c] = bv * rs;
    }
  }
}

// ---------------------------------------------------------------------------
// Kernel 3: fused strip attention + 3x3 depthwise dynamic conv + bias
// grid (8 heads, 6 wblks, 16 batches), 384 threads (one query row each)
// dynamic smem: K tile (384x16) + haloed V tile (50x10x16)
// ---------------------------------------------------------------------------
__global__ void __launch_bounds__(SEQ)
attn_kernel(const float* __restrict__ q, const float* __restrict__ k,
            const float* __restrict__ v, float* __restrict__ out){
  extern __shared__ float smem[];
  float* sK = smem;              // 6144 floats
  float* sV = smem + SEQ*HD;     // 8000 floats (halo layout [50][10][16])
  __shared__ float sW[HD*9];
  __shared__ float sB[HD];

  const int head = blockIdx.x, wblk = blockIdx.y, b = blockIdx.z;
  const int c0 = head*HD;
  const int wb0 = wblk*SSW;
  const int tid = threadIdx.x;
  const size_t bbase = (size_t)b*LL*CC;

  // load K tile
  for (int i = tid; i < SEQ*HD; i += SEQ){
    int j = i >> 4, d = i & 15;
    int hj = j >> 3, wj = j & 7;
    sK[i] = k[bbase + (size_t)(hj*WWD + wb0 + wj)*CC + c0 + d];
  }
  // load haloed V tile (zero at image border; halo cols come from neighbor strips)
  for (int i = tid; i < 50*10*16; i += SEQ){
    int pos = i >> 4, d = i & 15;
    int hh = pos / 10, ww = pos - hh*10;
    int gh = hh - 1, gw = wb0 + ww - 1;
    float val = 0.f;
    if (gh >= 0 && gh < HH && gw >= 0 && gw < WWD)
      val = v[bbase + (size_t)(gh*WWD + gw)*CC + c0 + d];
    sV[i] = val;
  }
  if (tid < HD*9) sW[tid] = g_w[(b*CC + c0 + tid/9)*9 + (tid % 9)];
  if (tid < HD)   sB[tid] = g_bias[b*CC + c0 + tid];
  __syncthreads();

  const int h = tid >> 3, wsl = tid & 7;
  const size_t orow = bbase + (size_t)(h*WWD + wb0 + wsl)*CC + c0;

  // q prescaled by scale * log2(e) so softmax uses a single EX2 per key
  ull q2[8];
  {
    const float SCL = 0.36067376022224085f;  // 0.25 * log2(e)
    const float2* qp = (const float2*)(q + orow);
    #pragma unroll
    for (int i = 0; i < 8; i++){ float2 t = qp[i]; q2[i] = pack2(t.x*SCL, t.y*SCL); }
  }
  ull acc[8];
  #pragma unroll
  for (int i = 0; i < 8; i++) acc[i] = 0ull;
  float lsum = 0.f;
  const ull z64 = 0ull;

  for (int hj = 0; hj < HH; hj++){
    const float* krow = sK + hj*8*HD;
    const float* vrow = sV + (hj*10 + 11)*HD;
    #pragma unroll
    for (int wj = 0; wj < 8; wj++){
      const ulonglong2* kp = (const ulonglong2*)(krow + wj*HD);
      ulonglong2 ka = kp[0], kb = kp[1], kc = kp[2], kd = kp[3];
      ull s2 = ffma2(q2[0], ka.x, z64);
      s2 = ffma2(q2[1], ka.y, s2);
      s2 = ffma2(q2[2], kb.x, s2);
      s2 = ffma2(q2[3], kb.y, s2);
      s2 = ffma2(q2[4], kc.x, s2);
      s2 = ffma2(q2[5], kc.y, s2);
      s2 = ffma2(q2[6], kd.x, s2);
      s2 = ffma2(q2[7], kd.y, s2);
      float2 sf = unpack2(s2);
      float p = ex2f(sf.x + sf.y);       // exp(score*scale); scores bounded, no max needed
      lsum += p;
      ull pp = pack2(p, p);
      const ulonglong2* vp = (const ulonglong2*)(vrow + wj*HD);
      ulonglong2 va = vp[0], vb2 = vp[1], vc = vp[2], vd = vp[3];
      acc[0] = ffma2(pp, va.x,  acc[0]);
      acc[1] = ffma2(pp, va.y,  acc[1]);
      acc[2] = ffma2(pp, vb2.x, acc[2]);
      acc[3] = ffma2(pp, vb2.y, acc[3]);
      acc[4] = ffma2(pp, vc.x,  acc[4]);
      acc[5] = ffma2(pp, vc.y,  acc[5]);
      acc[6] = ffma2(pp, vd.x,  acc[6]);
      acc[7] = ffma2(pp, vd.y,  acc[7]);
    }
  }

  // depthwise 3x3 dynamic conv + dynamic bias (from haloed sV)
  float pacc[16];
  #pragma unroll
  for (int d = 0; d < 16; d++) pacc[d] = sB[d];
  #pragma unroll
  for (int t = 0; t < 9; t++){
    int dy = t / 3, dx = t - dy*3;
    const float* vp = sV + ((h+dy)*10 + wsl + dx)*HD;
    #pragma unroll
    for (int d = 0; d < 16; d++) pacc[d] += sW[d*9 + t] * vp[d];
  }

  float rinv = 1.0f / lsum;
  float2* op = (float2*)(out + orow);
  #pragma unroll
  for (int i = 0; i < 8; i++){
    float2 a = unpack2(acc[i]);
    float2 o2;
    o2.x = a.x*rinv + pacc[2*i];
    o2.y = a.y*rinv + pacc[2*i+1];
    op[i] = o2;
  }
}

// ---------------------------------------------------------------------------
extern "C" void kernel_launch(void* const* d_in, const int* in_sizes, int n_in,
                              void* d_out, int out_size){
  const float* q    = (const float*)d_in[0];
  const float* k    = (const float*)d_in[1];
  const float* v    = (const float*)d_in[2];
  const float* p1w  = (const float*)d_in[3];
  const float* p1b  = (const float*)d_in[4];
  const float* bng  = (const float*)d_in[5];
  const float* bnb  = (const float*)d_in[6];
  const float* bnm  = (const float*)d_in[7];
  const float* bnv  = (const float*)d_in[8];
  const float* p2w  = (const float*)d_in[9];
  const float* p2b  = (const float*)d_in[10];
  const float* dynw = (const float*)d_in[11];
  const float* dynb = (const float*)d_in[12];
  float* out = (float*)d_out;

  // idempotent, deterministic attribute sets (not allocations)
  cudaFuncSetAttribute(proj_kernel, cudaFuncAttributeMaxDynamicSharedMemorySize, 90112);
  cudaFuncSetAttribute(attn_kernel, cudaFuncAttributeMaxDynamicSharedMemorySize, 57600);

  pool_kernel<<<dim3(9, BB), 256>>>(v);
  proj_kernel<<<BB, 256, 88320>>>(p1w, p1b, bng, bnb, bnm, bnv, p2w, p2b, dynw, dynb);
  attn_kernel<<<dim3(NHH, NWIN, BB), SEQ, 56576>>>(q, k, v, out);
}

// round 2
// speedup vs baseline: 1.2740x; 1.2740x over previous
#include <cuda_runtime.h>
#include <cuda_bf16.h>
#include <cstdint>

#define BB 16
#define HH 48
#define WWD 48
#define CC 128
#define GG 4
#define NHH 8
#define SSW 8
#define LL (HH*WWD)          // 2304
#define HD (CC/NHH)          // 16
#define NWIN (WWD/SSW)       // 6
#define SEQ (HH*SSW)         // 384

// scratch (no allocations allowed)
__device__ float g_pooled[BB*9*CC];
__device__ float g_w[BB*CC*9];
__device__ float g_bias[BB*CC];

typedef unsigned long long ull;

__device__ __forceinline__ ull ffma2(ull a, ull b, ull c){
  ull d; asm("fma.rn.f32x2 %0,%1,%2,%3;" : "=l"(d) : "l"(a), "l"(b), "l"(c)); return d;
}
__device__ __forceinline__ ull fadd2(ull a, ull b){
  ull d; asm("add.rn.f32x2 %0,%1,%2;" : "=l"(d) : "l"(a), "l"(b)); return d;
}
__device__ __forceinline__ ull pack2(float lo, float hi){
  ull r; asm("mov.b64 %0,{%1,%2};" : "=l"(r) : "f"(lo), "f"(hi)); return r;
}
__device__ __forceinline__ float2 unpack2(ull a){
  float2 r; asm("mov.b64 {%0,%1},%2;" : "=f"(r.x), "=f"(r.y) : "l"(a)); return r;
}
__device__ __forceinline__ float ex2f(float x){
  float r; asm("ex2.approx.ftz.f32 %0,%1;" : "=f"(r) : "f"(x)); return r;
}

// ---------------------------------------------------------------------------
// Kernel 1: adaptive avg pool to 3x3 (uniform 16x16 block means), float4 loads
// grid (9 bins, 16 batches), 256 threads: part = tid>>5 covers 2 rows each
// ---------------------------------------------------------------------------
__global__ void pool_kernel(const float* __restrict__ v){
  const int bin = blockIdx.x, b = blockIdx.y;
  const int ky = bin / 3, kx = bin - ky*3;
  const int tid = threadIdx.x;
  const int c4 = tid & 31, part = tid >> 5;   // c4: float4 channel group
  const float4* vb = (const float4*)(v + (size_t)b*LL*CC);
  float4 s = make_float4(0.f,0.f,0.f,0.f);
  #pragma unroll
  for (int r = 0; r < 2; r++){
    const int h = ky*16 + part*2 + r;
    const float4* row = vb + (size_t)(h*WWD + kx*16)*(CC/4) + c4;
    #pragma unroll
    for (int ww = 0; ww < 16; ww++){
      float4 t = row[ww*(CC/4)];
      s.x += t.x; s.y += t.y; s.z += t.z; s.w += t.w;
    }
  }
  __shared__ float4 red[256];
  red[tid] = s; __syncthreads();
  if (tid < 128){ float4 o = red[tid+128]; s.x+=o.x; s.y+=o.y; s.z+=o.z; s.w+=o.w; red[tid]=s; }
  __syncthreads();
  if (tid < 64){ s = red[tid]; float4 o = red[tid+64]; s.x+=o.x; s.y+=o.y; s.z+=o.z; s.w+=o.w; red[tid]=s; }
  __syncthreads();
  if (tid < 32){
    s = red[tid]; float4 o = red[tid+32];
    s.x = (s.x+o.x)*(1.f/256.f); s.y = (s.y+o.y)*(1.f/256.f);
    s.z = (s.z+o.z)*(1.f/256.f); s.w = (s.w+o.w)*(1.f/256.f);
    ((float4*)g_pooled)[(b*9 + bin)*32 + tid] = s;
  }
}

// ---------------------------------------------------------------------------
// Kernel 2: proj1 -> BN -> GELU -> proj2 -> softmax over G -> dyn w / bias
// grid 16 (batch), 256 threads, dynamic smem
// ---------------------------------------------------------------------------
__global__ void proj_kernel(const float* __restrict__ p1w, const float* __restrict__ p1b,
                            const float* __restrict__ bng, const float* __restrict__ bnb,
                            const float* __restrict__ bnm, const float* __restrict__ bnv,
                            const float* __restrict__ p2w, const float* __restrict__ p2b,
                            const float* __restrict__ dynw, const float* __restrict__ dynb){
  const int b = blockIdx.x, tid = threadIdx.x;
  extern __shared__ float ps[];
  float* pp  = ps;             // 10*128  (pos 9 = global mean)
  float* act = pp + 1280;      // 10*32
  float* p1t = act + 320;      // [c][o]  128*32
  float* w2t = p1t + 4096;     // [o][oc] 32*512

  for (int i = tid; i < 9*CC; i += 256) pp[i] = g_pooled[b*9*CC + i];
  for (int i = tid; i < 4096; i += 256){ int o = i >> 7, c = i & 127; p1t[c*32+o] = p1w[i]; }
  for (int i = tid; i < 16384; i += 256){ int oc = i >> 5, o = i & 31; w2t[o*512+oc] = p2w[i]; }
  __syncthreads();
  if (tid < 128){
    float s = 0.f;
    #pragma unroll
    for (int qq = 0; qq < 9; qq++) s += pp[qq*CC + tid];
    pp[9*CC + tid] = s * (1.f/9.f);
  }
  __syncthreads();

  // stage A: 10 positions x 32 outputs
  for (int t = tid; t < 320; t += 256){
    int pos = t >> 5, o = t & 31;
    float s = p1b[o];
    const float* prow = pp + pos*CC;
    #pragma unroll 8
    for (int cc = 0; cc < CC; cc++) s += p1t[cc*32+o] * prow[cc];
    float inv = rsqrtf(bnv[o] + 1e-5f);
    s = (s - bnm[o]) * (inv * bng[o]) + bnb[o];
    s = 0.5f * s * (1.f + erff(s * 0.70710678118654752f));
    act[pos*32+o] = s;
  }
  __syncthreads();

  // stage B: 10 positions x 128 channels: 4 group scores -> softmax -> combine
  for (int t = tid; t < 1280; t += 256){
    int pos = t >> 7, c = t & 127;
    float y[4];
    #pragma unroll
    for (int g = 0; g < 4; g++){
      int oc = g*CC + c;
      float s = p2b[oc];
      #pragma unroll
      for (int o = 0; o < 32; o++) s += w2t[o*512+oc] * act[pos*32+o];
      y[g] = s;
    }
    float m = fmaxf(fmaxf(y[0],y[1]), fmaxf(y[2],y[3]));
    float e0 = expf(y[0]-m), e1 = expf(y[1]-m), e2 = expf(y[2]-m), e3 = expf(y[3]-m);
    float rs = 1.f / (e0+e1+e2+e3);
    if (pos < 9){
      float wv = e0*dynw[(0*CC+c)*9+pos] + e1*dynw[(1*CC+c)*9+pos]
               + e2*dynw[(2*CC+c)*9+pos] + e3*dynw[(3*CC+c)*9+pos];
      g_w[(b*CC + c)*9 + pos] = wv * rs;
    } else {
      float bv = e0*dynb[0*CC+c] + e1*dynb[1*CC+c] + e2*dynb[2*CC+c] + e3*dynb[3*CC+c];
      g_bias[b*CC + c] = bv * rs;
    }
  }
}

// ---------------------------------------------------------------------------
// Kernel 3: fused strip attention + 3x3 depthwise dynamic conv + bias
// grid (8 heads, 6 wblks, 16 batches), 192 threads
// Each thread handles 2 query rows (h, h+24), same strip column ->
// every K/V smem read is amortized over both queries.
// dynamic smem: K tile (384x16) + haloed V tile (50x10x16) + packed conv w/b
// ---------------------------------------------------------------------------
__global__ void __launch_bounds__(192, 3)
attn_kernel(const float* __restrict__ q, const float* __restrict__ k,
            const float* __restrict__ v, float* __restrict__ out){
  extern __shared__ float smem[];
  float* sK = smem;                 // 6144 floats
  float* sV = smem + SEQ*HD;        // 8000 floats, halo layout [50][10][16]
  ull*  sW2 = (ull*)(smem + 14144); // [9][8] packed channel-pairs
  ull*  sB2 = sW2 + 72;             // [8]

  const int head = blockIdx.x, wblk = blockIdx.y, b = blockIdx.z;
  const int c0 = head*HD;
  const int wb0 = wblk*SSW;
  const int tid = threadIdx.x;
  const size_t bbase = (size_t)b*LL*CC;

  // ---- q loads first (global, overlap with smem fills) ----
  const int h0 = tid >> 3, wsl = tid & 7;   // h0 in 0..23
  const int h1 = h0 + 24;
  const size_t orow0 = bbase + (size_t)(h0*WWD + wb0 + wsl)*CC + c0;
  const size_t orow1 = bbase + (size_t)(h1*WWD + wb0 + wsl)*CC + c0;
  ull q2a[8], q2b[8];
  {
    const float SCL = 0.36067376022224085f;  // 0.25 * log2(e)
    const float2* qa = (const float2*)(q + orow0);
    const float2* qb = (const float2*)(q + orow1);
    #pragma unroll
    for (int i = 0; i < 8; i++){
      float2 t = qa[i]; q2a[i] = pack2(t.x*SCL, t.y*SCL);
      float2 u = qb[i]; q2b[i] = pack2(u.x*SCL, u.y*SCL);
    }
  }

  // ---- fill K tile (float4) ----
  {
    float4* sK4 = (float4*)sK;
    for (int i = tid; i < SEQ*HD/4; i += 192){
      int j = i >> 2, qd = i & 3;            // key j, float4 slot
      int hj = j >> 3, wj = j & 7;
      sK4[i] = *(const float4*)(k + bbase + (size_t)(hj*WWD + wb0 + wj)*CC + c0 + qd*4);
    }
  }
  // ---- fill haloed V tile (float4, zero at image border) ----
  {
    float4* sV4 = (float4*)sV;
    for (int i = tid; i < 500*4; i += 192){
      int pos = i >> 2, qd = i & 3;
      int hh = pos / 10, ww = pos - hh*10;
      int gh = hh - 1, gw = wb0 + ww - 1;
      float4 val = make_float4(0.f,0.f,0.f,0.f);
      if (gh >= 0 && gh < HH && gw >= 0 && gw < WWD)
        val = *(const float4*)(v + bbase + (size_t)(gh*WWD + gw)*CC + c0 + qd*4);
      sV4[i] = val;
    }
  }
  if (tid < 72){
    int t = tid >> 3, i = tid & 7;
    sW2[t*8+i] = pack2(g_w[(b*CC + c0 + 2*i  )*9 + t],
                       g_w[(b*CC + c0 + 2*i+1)*9 + t]);
  }
  if (tid < 8)
    sB2[tid] = pack2(g_bias[b*CC + c0 + 2*tid], g_bias[b*CC + c0 + 2*tid+1]);
  __syncthreads();

  ull accA[8], accB[8];
  #pragma unroll
  for (int i = 0; i < 8; i++){ accA[i] = 0ull; accB[i] = 0ull; }
  float lsumA = 0.f, lsumB = 0.f;
  const ull z64 = 0ull;

  for (int hj = 0; hj < HH; hj++){
    const ulonglong2* krow = (const ulonglong2*)(sK + hj*8*HD);
    const ulonglong2* vrow = (const ulonglong2*)(sV + (hj*10 + 11)*HD);
    #pragma unroll
    for (int wj = 0; wj < 8; wj++){
      ulonglong2 k0 = krow[wj*4+0], k1 = krow[wj*4+1];
      ulonglong2 k2 = krow[wj*4+2], k3 = krow[wj*4+3];
      // query A dot: two 4-deep chains
      ull sa0 = ffma2(q2a[0], k0.x, z64);
      ull sa1 = ffma2(q2a[1], k0.y, z64);
      sa0 = ffma2(q2a[2], k1.x, sa0);
      sa1 = ffma2(q2a[3], k1.y, sa1);
      sa0 = ffma2(q2a[4], k2.x, sa0);
      sa1 = ffma2(q2a[5], k2.y, sa1);
      sa0 = ffma2(q2a[6], k3.x, sa0);
      sa1 = ffma2(q2a[7], k3.y, sa1);
      // query B dot
      ull sb0 = ffma2(q2b[0], k0.x, z64);
      ull sb1 = ffma2(q2b[1], k0.y, z64);
      sb0 = ffma2(q2b[2], k1.x, sb0);
      sb1 = ffma2(q2b[3], k1.y, sb1);
      sb0 = ffma2(q2b[4], k2.x, sb0);
      sb1 = ffma2(q2b[5], k2.y, sb1);
      sb0 = ffma2(q2b[6], k3.x, sb0);
      sb1 = ffma2(q2b[7], k3.y, sb1);
      float2 fa = unpack2(fadd2(sa0, sa1));
      float2 fb = unpack2(fadd2(sb0, sb1));
      float pA = ex2f(fa.x + fa.y);   // exp(score*scale); scores bounded, no max pass
      float pB = ex2f(fb.x + fb.y);
      lsumA += pA; lsumB += pB;
      ull ppA = pack2(pA, pA), ppB = pack2(pB, pB);
      ulonglong2 v0 = vrow[wj*4+0], v1 = vrow[wj*4+1];
      ulonglong2 v2 = vrow[wj*4+2], v3 = vrow[wj*4+3];
      accA[0] = ffma2(ppA, v0.x, accA[0]);  accB[0] = ffma2(ppB, v0.x, accB[0]);
      accA[1] = ffma2(ppA, v0.y, accA[1]);  accB[1] = ffma2(ppB, v0.y, accB[1]);
      accA[2] = ffma2(ppA, v1.x, accA[2]);  accB[2] = ffma2(ppB, v1.x, accB[2]);
      accA[3] = ffma2(ppA, v1.y, accA[3]);  accB[3] = ffma2(ppB, v1.y, accB[3]);
      accA[4] = ffma2(ppA, v2.x, accA[4]);  accB[4] = ffma2(ppB, v2.x, accB[4]);
      accA[5] = ffma2(ppA, v2.y, accA[5]);  accB[5] = ffma2(ppB, v2.y, accB[5]);
      accA[6] = ffma2(ppA, v3.x, accA[6]);  accB[6] = ffma2(ppB, v3.x, accB[6]);
      accA[7] = ffma2(ppA, v3.y, accA[7]);  accB[7] = ffma2(ppB, v3.y, accB[7]);
    }
  }

  // ---- depthwise 3x3 dynamic conv + dynamic bias (packed f32x2) ----
  ull pacc0[8], pacc1[8];
  #pragma unroll
  for (int i = 0; i < 8; i++){ pacc0[i] = sB2[i]; pacc1[i] = sB2[i]; }
  #pragma unroll
  for (int t = 0; t < 9; t++){
    int dy = t / 3, dx = t - dy*3;
    const ulonglong2* vpA = (const ulonglong2*)(sV + ((h0+dy)*10 + wsl + dx)*HD);
    const ulonglong2* vpB = (const ulonglong2*)(sV + ((h1+dy)*10 + wsl + dx)*HD);
    ulonglong2 a0 = vpA[0], a1 = vpA[1], a2 = vpA[2], a3 = vpA[3];
    ulonglong2 b0 = vpB[0], b1 = vpB[1], b2 = vpB[2], b3 = vpB[3];
    pacc0[0] = ffma2(sW2[t*8+0], a0.x, pacc0[0]);  pacc1[0] = ffma2(sW2[t*8+0], b0.x, pacc1[0]);
    pacc0[1] = ffma2(sW2[t*8+1], a0.y, pacc0[1]);  pacc1[1] = ffma2(sW2[t*8+1], b0.y, pacc1[1]);
    pacc0[2] = ffma2(sW2[t*8+2], a1.x, pacc0[2]);  pacc1[2] = ffma2(sW2[t*8+2], b1.x, pacc1[2]);
    pacc0[3] = ffma2(sW2[t*8+3], a1.y, pacc0[3]);  pacc1[3] = ffma2(sW2[t*8+3], b1.y, pacc1[3]);
    pacc0[4] = ffma2(sW2[t*8+4], a2.x, pacc0[4]);  pacc1[4] = ffma2(sW2[t*8+4], b2.x, pacc1[4]);
    pacc0[5] = ffma2(sW2[t*8+5], a2.y, pacc0[5]);  pacc1[5] = ffma2(sW2[t*8+5], b2.y, pacc1[5]);
    pacc0[6] = ffma2(sW2[t*8+6], a3.x, pacc0[6]);  pacc1[6] = ffma2(sW2[t*8+6], b3.x, pacc1[6]);
    pacc0[7] = ffma2(sW2[t*8+7], a3.y, pacc0[7]);  pacc1[7] = ffma2(sW2[t*8+7], b3.y, pacc1[7]);
  }

  float rA = 1.0f / lsumA, rB = 1.0f / lsumB;
  ull rA2 = pack2(rA, rA), rB2 = pack2(rB, rB);
  ulonglong2* opA = (ulonglong2*)(out + orow0);
  ulonglong2* opB = (ulonglong2*)(out + orow1);
  #pragma unroll
  for (int i = 0; i < 4; i++){
    ulonglong2 oa, ob;
    oa.x = ffma2(accA[2*i],   rA2, pacc0[2*i]);
    oa.y = ffma2(accA[2*i+1], rA2, pacc0[2*i+1]);
    ob.x = ffma2(accB[2*i],   rB2, pacc1[2*i]);
    ob.y = ffma2(accB[2*i+1], rB2, pacc1[2*i+1]);
    opA[i] = oa;
    opB[i] = ob;
  }
}

// ---------------------------------------------------------------------------
extern "C" void kernel_launch(void* const* d_in, const int* in_sizes, int n_in,
                              void* d_out, int out_size){
  const float* q    = (const float*)d_in[0];
  const float* k    = (const float*)d_in[1];
  const float* v    = (const float*)d_in[2];
  const float* p1w  = (const float*)d_in[3];
  const float* p1b  = (const float*)d_in[4];
  const float* bng  = (const float*)d_in[5];
  const float* bnb  = (const float*)d_in[6];
  const float* bnm  = (const float*)d_in[7];
  const float* bnv  = (const float*)d_in[8];
  const float* p2w  = (const float*)d_in[9];
  const float* p2b  = (const float*)d_in[10];
  const float* dynw = (const float*)d_in[11];
  const float* dynb = (const float*)d_in[12];
  float* out = (float*)d_out;

  cudaFuncSetAttribute(proj_kernel, cudaFuncAttributeMaxDynamicSharedMemorySize, 90112);
  cudaFuncSetAttribute(attn_kernel, cudaFuncAttributeMaxDynamicSharedMemorySize, 57344);

  pool_kernel<<<dim3(9, BB), 256>>>(v);
  proj_kernel<<<BB, 256, 88320>>>(p1w, p1b, bng, bnb, bnm, bnv, p2w, p2b, dynw, dynb);
  attn_kernel<<<dim3(NHH, NWIN, BB), 192, 57280>>>(q, k, v, out);
}

// round 3
// speedup vs baseline: 1.4448x; 1.1340x over previous
#include <cuda_runtime.h>
#include <cuda_bf16.h>
#include <cstdint>

#define BB 16
#define HH 48
#define WWD 48
#define CC 128
#define GG 4
#define NHH 8
#define SSW 8
#define LL (HH*WWD)          // 2304
#define HD (CC/NHH)          // 16
#define NWIN (WWD/SSW)       // 6
#define SEQ (HH*SSW)         // 384

// scratch (no allocations allowed)
__device__ float g_pooled[BB*9*CC];
__device__ float g_w[BB*CC*9];
__device__ float g_bias[BB*CC];

typedef unsigned long long ull;

__device__ __forceinline__ ull ffma2(ull a, ull b, ull c){
  ull d; asm("fma.rn.f32x2 %0,%1,%2,%3;" : "=l"(d) : "l"(a), "l"(b), "l"(c)); return d;
}
__device__ __forceinline__ ull fadd2(ull a, ull b){
  ull d; asm("add.rn.f32x2 %0,%1,%2;" : "=l"(d) : "l"(a), "l"(b)); return d;
}
__device__ __forceinline__ ull pack2(float lo, float hi){
  ull r; asm("mov.b64 %0,{%1,%2};" : "=l"(r) : "f"(lo), "f"(hi)); return r;
}
__device__ __forceinline__ float2 unpack2(ull a){
  float2 r; asm("mov.b64 {%0,%1},%2;" : "=f"(r.x), "=f"(r.y) : "l"(a)); return r;
}
__device__ __forceinline__ float ex2f(float x){
  float r; asm("ex2.approx.ftz.f32 %0,%1;" : "=f"(r) : "f"(x)); return r;
}
__device__ __forceinline__ void ld8(ull* dst, const ulonglong2* p){
  ulonglong2 a = p[0], b = p[1], c = p[2], d = p[3];
  dst[0]=a.x; dst[1]=a.y; dst[2]=b.x; dst[3]=b.y;
  dst[4]=c.x; dst[5]=c.y; dst[6]=d.x; dst[7]=d.y;
}

// ---------------------------------------------------------------------------
// Kernel 1: adaptive avg pool to 3x3 (uniform 16x16 block means)
// grid (9 bins, 16 batches, 2 channel halves), 256 threads
// thread = (part row 0..15) x (16 float4 channel groups); 16-wide MLP each
// ---------------------------------------------------------------------------
__global__ void pool_kernel(const float* __restrict__ v){
  const int bin = blockIdx.x, b = blockIdx.y, ch = blockIdx.z;
  const int ky = bin / 3, kx = bin - ky*3;
  const int tid = threadIdx.x;
  const int c4 = tid & 15, part = tid >> 4;        // 16 rows, 16 c4-groups
  const int cg = ch*16 + c4;                       // float4 channel group 0..31
  const float4* vb = (const float4*)(v + (size_t)b*LL*CC);
  const int h = ky*16 + part;
  const float4* row = vb + (size_t)(h*WWD + kx*16)*(CC/4) + cg;
  float4 s = make_float4(0.f,0.f,0.f,0.f);
  #pragma unroll
  for (int ww = 0; ww < 16; ww++){
    float4 t = row[ww*(CC/4)];
    s.x += t.x; s.y += t.y; s.z += t.z; s.w += t.w;
  }
  __shared__ float4 red[256];
  red[tid] = s; __syncthreads();
  #pragma unroll
  for (int off = 128; off >= 16; off >>= 1){
    if (tid < off){
      float4 o = red[tid+off];
      s.x += o.x; s.y += o.y; s.z += o.z; s.w += o.w;
      red[tid] = s;
    }
    __syncthreads();
  }
  if (tid < 16){
    s.x *= (1.f/256.f); s.y *= (1.f/256.f); s.z *= (1.f/256.f); s.w *= (1.f/256.f);
    ((float4*)g_pooled)[(b*9 + bin)*32 + ch*16 + tid] = s;
  }
}

// ---------------------------------------------------------------------------
// Kernel 2: proj1 -> BN -> GELU -> proj2 -> softmax over G -> dyn w / bias
// grid 16 (batch), 256 threads, dynamic smem
// ---------------------------------------------------------------------------
__global__ void proj_kernel(const float* __restrict__ p1w, const float* __restrict__ p1b,
                            const float* __restrict__ bng, const float* __restrict__ bnb,
                            const float* __restrict__ bnm, const float* __restrict__ bnv,
                            const float* __restrict__ p2w, const float* __restrict__ p2b,
                            const float* __restrict__ dynw, const float* __restrict__ dynb){
  const int b = blockIdx.x, tid = threadIdx.x;
  extern __shared__ float ps[];
  float* pp  = ps;             // 10*128  (pos 9 = global mean)
  float* act = pp + 1280;      // 10*32
  float* p1t = act + 320;      // [c][o]  128*32
  float* w2t = p1t + 4096;     // [o][oc] 32*512

  for (int i = tid; i < 9*CC; i += 256) pp[i] = g_pooled[b*9*CC + i];
  for (int i = tid; i < 4096; i += 256){ int o = i >> 7, c = i & 127; p1t[c*32+o] = p1w[i]; }
  for (int i = tid; i < 16384; i += 256){ int oc = i >> 5, o = i & 31; w2t[o*512+oc] = p2w[i]; }
  __syncthreads();
  if (tid < 128){
    float s = 0.f;
    #pragma unroll
    for (int qq = 0; qq < 9; qq++) s += pp[qq*CC + tid];
    pp[9*CC + tid] = s * (1.f/9.f);
  }
  __syncthreads();

  // stage A: 10 positions x 32 outputs
  for (int t = tid; t < 320; t += 256){
    int pos = t >> 5, o = t & 31;
    float s = p1b[o];
    const float* prow = pp + pos*CC;
    #pragma unroll 8
    for (int cc = 0; cc < CC; cc++) s += p1t[cc*32+o] * prow[cc];
    float inv = rsqrtf(bnv[o] + 1e-5f);
    s = (s - bnm[o]) * (inv * bng[o]) + bnb[o];
    s = 0.5f * s * (1.f + erff(s * 0.70710678118654752f));
    act[pos*32+o] = s;
  }
  __syncthreads();

  // stage B: 10 positions x 128 channels: 4 group scores -> softmax -> combine
  for (int t = tid; t < 1280; t += 256){
    int pos = t >> 7, c = t & 127;
    float y[4];
    #pragma unroll
    for (int g = 0; g < 4; g++){
      int oc = g*CC + c;
      float s = p2b[oc];
      #pragma unroll
      for (int o = 0; o < 32; o++) s += w2t[o*512+oc] * act[pos*32+o];
      y[g] = s;
    }
    float m = fmaxf(fmaxf(y[0],y[1]), fmaxf(y[2],y[3]));
    float e0 = expf(y[0]-m), e1 = expf(y[1]-m), e2 = expf(y[2]-m), e3 = expf(y[3]-m);
    float rs = 1.f / (e0+e1+e2+e3);
    if (pos < 9){
      float wv = e0*dynw[(0*CC+c)*9+pos] + e1*dynw[(1*CC+c)*9+pos]
               + e2*dynw[(2*CC+c)*9+pos] + e3*dynw[(3*CC+c)*9+pos];
      g_w[(b*CC + c)*9 + pos] = wv * rs;
    } else {
      float bv = e0*dynb[0*CC+c] + e1*dynb[1*CC+c] + e2*dynb[2*CC+c] + e3*dynb[3*CC+c];
      g_bias[b*CC + c] = bv * rs;
    }
  }
}

// ---------------------------------------------------------------------------
// Kernel 3: fused strip attention + 3x3 depthwise dynamic conv + bias
// grid (8 heads, 6 wblks, 16 batches), 192 threads, 2 CTAs/SM (170-reg budget)
// Each thread: 2 query rows (h, h+24). Ping-pong register prefetch of next
// key's K/V rows so LDS latency never exposes.
// ---------------------------------------------------------------------------
__global__ void __launch_bounds__(192, 2)
attn_kernel(const float* __restrict__ q, const float* __restrict__ k,
            const float* __restrict__ v, float* __restrict__ out){
  extern __shared__ float smem[];
  float* sK = smem;                 // 6144 floats
  float* sV = smem + SEQ*HD;        // 8000 floats, halo layout [50][10][16]
  ull*  sW2 = (ull*)(smem + 14144); // [9][8] packed channel-pairs
  ull*  sB2 = sW2 + 72;             // [8]

  const int head = blockIdx.x, wblk = blockIdx.y, b = blockIdx.z;
  const int c0 = head*HD;
  const int wb0 = wblk*SSW;
  const int tid = threadIdx.x;
  const size_t bbase = (size_t)b*LL*CC;

  // ---- q loads (global, overlap with smem fills) ----
  const int h0 = tid >> 3, wsl = tid & 7;   // h0 in 0..23
  const int h1 = h0 + 24;
  const size_t orow0 = bbase + (size_t)(h0*WWD + wb0 + wsl)*CC + c0;
  const size_t orow1 = bbase + (size_t)(h1*WWD + wb0 + wsl)*CC + c0;
  ull q2a[8], q2b[8];
  {
    const float SCL = 0.36067376022224085f;  // 0.25 * log2(e)
    const float4* qa = (const float4*)(q + orow0);
    const float4* qb = (const float4*)(q + orow1);
    #pragma unroll
    for (int i = 0; i < 4; i++){
      float4 t = qa[i];
      q2a[2*i]   = pack2(t.x*SCL, t.y*SCL);
      q2a[2*i+1] = pack2(t.z*SCL, t.w*SCL);
      float4 u = qb[i];
      q2b[2*i]   = pack2(u.x*SCL, u.y*SCL);
      q2b[2*i+1] = pack2(u.z*SCL, u.w*SCL);
    }
  }

  // ---- fill K tile (float4) ----
  {
    float4* sK4 = (float4*)sK;
    for (int i = tid; i < SEQ*HD/4; i += 192){
      int j = i >> 2, qd = i & 3;
      int hj = j >> 3, wj = j & 7;
      sK4[i] = *(const float4*)(k + bbase + (size_t)(hj*WWD + wb0 + wj)*CC + c0 + qd*4);
    }
  }
  // ---- fill haloed V tile (float4, zero at image border) ----
  {
    float4* sV4 = (float4*)sV;
    for (int i = tid; i < 500*4; i += 192){
      int pos = i >> 2, qd = i & 3;
      int hh = pos / 10, ww = pos - hh*10;
      int gh = hh - 1, gw = wb0 + ww - 1;
      float4 val = make_float4(0.f,0.f,0.f,0.f);
      if (gh >= 0 && gh < HH && gw >= 0 && gw < WWD)
        val = *(const float4*)(v + bbase + (size_t)(gh*WWD + gw)*CC + c0 + qd*4);
      sV4[i] = val;
    }
  }
  if (tid < 72){
    int t = tid >> 3, i = tid & 7;
    sW2[t*8+i] = pack2(g_w[(b*CC + c0 + 2*i  )*9 + t],
                       g_w[(b*CC + c0 + 2*i+1)*9 + t]);
  }
  if (tid < 8)
    sB2[tid] = pack2(g_bias[b*CC + c0 + 2*tid], g_bias[b*CC + c0 + 2*tid+1]);
  __syncthreads();

  ull accA[8], accB[8];
  #pragma unroll
  for (int i = 0; i < 8; i++){ accA[i] = 0ull; accB[i] = 0ull; }
  ull lsum2 = 0ull;
  const ull z64 = 0ull;

  const ulonglong2* sK2 = (const ulonglong2*)sK;   // key j at sK2 + j*4
  const ulonglong2* sV2 = (const ulonglong2*)sV;   // key (hj,wj) at (hj*10+wj+11)*4

  // ping-pong register buffers
  ull kb[2][8], vb2[2][8];
  ld8(kb[0],  sK2);
  ld8(vb2[0], sV2 + 11*4);

  for (int hj = 0; hj < HH; hj++){
    #pragma unroll
    for (int wj = 0; wj < 8; wj++){
      const int cur = wj & 1, nxt = cur ^ 1;
      // prefetch next key's K/V rows
      if (wj < 7){
        ld8(kb[nxt],  sK2 + (hj*8 + wj + 1)*4);
        ld8(vb2[nxt], sV2 + (hj*10 + wj + 12)*4);
      } else if (hj < HH-1){
        ld8(kb[nxt],  sK2 + (hj+1)*32);
        ld8(vb2[nxt], sV2 + ((hj+1)*10 + 11)*4);
      }
      const ull* kc = kb[cur];
      const ull* vc = vb2[cur];
      // query A dot: two 4-deep chains
      ull sa0 = ffma2(q2a[0], kc[0], z64);
      ull sa1 = ffma2(q2a[1], kc[1], z64);
      sa0 = ffma2(q2a[2], kc[2], sa0);
      sa1 = ffma2(q2a[3], kc[3], sa1);
      sa0 = ffma2(q2a[4], kc[4], sa0);
      sa1 = ffma2(q2a[5], kc[5], sa1);
      sa0 = ffma2(q2a[6], kc[6], sa0);
      sa1 = ffma2(q2a[7], kc[7], sa1);
      // query B dot
      ull sb0 = ffma2(q2b[0], kc[0], z64);
      ull sb1 = ffma2(q2b[1], kc[1], z64);
      sb0 = ffma2(q2b[2], kc[2], sb0);
      sb1 = ffma2(q2b[3], kc[3], sb1);
      sb0 = ffma2(q2b[4], kc[4], sb0);
      sb1 = ffma2(q2b[5], kc[5], sb1);
      sb0 = ffma2(q2b[6], kc[6], sb0);
      sb1 = ffma2(q2b[7], kc[7], sb1);
      float2 fa = unpack2(fadd2(sa0, sa1));
      float2 fb = unpack2(fadd2(sb0, sb1));
      float pA = ex2f(fa.x + fa.y);   // exp(score*scale); scores bounded, no max pass
      float pB = ex2f(fb.x + fb.y);
      lsum2 = fadd2(lsum2, pack2(pA, pB));
      ull ppA = pack2(pA, pA), ppB = pack2(pB, pB);
      accA[0] = ffma2(ppA, vc[0], accA[0]);  accB[0] = ffma2(ppB, vc[0], accB[0]);
      accA[1] = ffma2(ppA, vc[1], accA[1]);  accB[1] = ffma2(ppB, vc[1], accB[1]);
      accA[2] = ffma2(ppA, vc[2], accA[2]);  accB[2] = ffma2(ppB, vc[2], accB[2]);
      accA[3] = ffma2(ppA, vc[3], accA[3]);  accB[3] = ffma2(ppB, vc[3], accB[3]);
      accA[4] = ffma2(ppA, vc[4], accA[4]);  accB[4] = ffma2(ppB, vc[4], accB[4]);
      accA[5] = ffma2(ppA, vc[5], accA[5]);  accB[5] = ffma2(ppB, vc[5], accB[5]);
      accA[6] = ffma2(ppA, vc[6], accA[6]);  accB[6] = ffma2(ppB, vc[6], accB[6]);
      accA[7] = ffma2(ppA, vc[7], accA[7]);  accB[7] = ffma2(ppB, vc[7], accB[7]);
    }
  }

  // ---- depthwise 3x3 dynamic conv + dynamic bias (packed f32x2) ----
  ull pacc0[8], pacc1[8];
  #pragma unroll
  for (int i = 0; i < 8; i++){ pacc0[i] = sB2[i]; pacc1[i] = sB2[i]; }
  #pragma unroll
  for (int t = 0; t < 9; t++){
    int dy = t / 3, dx = t - dy*3;
    const ulonglong2* vpA = (const ulonglong2*)(sV + ((h0+dy)*10 + wsl + dx)*HD);
    const ulonglong2* vpB = (const ulonglong2*)(sV + ((h1+dy)*10 + wsl + dx)*HD);
    ulonglong2 a0 = vpA[0], a1 = vpA[1], a2 = vpA[2], a3 = vpA[3];
    ulonglong2 b0 = vpB[0], b1 = vpB[1], b2 = vpB[2], b3 = vpB[3];
    pacc0[0] = ffma2(sW2[t*8+0], a0.x, pacc0[0]);  pacc1[0] = ffma2(sW2[t*8+0], b0.x, pacc1[0]);
    pacc0[1] = ffma2(sW2[t*8+1], a0.y, pacc0[1]);  pacc1[1] = ffma2(sW2[t*8+1], b0.y, pacc1[1]);
    pacc0[2] = ffma2(sW2[t*8+2], a1.x, pacc0[2]);  pacc1[2] = ffma2(sW2[t*8+2], b1.x, pacc1[2]);
    pacc0[3] = ffma2(sW2[t*8+3], a1.y, pacc0[3]);  pacc1[3] = ffma2(sW2[t*8+3], b1.y, pacc1[3]);
    pacc0[4] = ffma2(sW2[t*8+4], a2.x, pacc0[4]);  pacc1[4] = ffma2(sW2[t*8+4], b2.x, pacc1[4]);
    pacc0[5] = ffma2(sW2[t*8+5], a2.y, pacc0[5]);  pacc1[5] = ffma2(sW2[t*8+5], b2.y, pacc1[5]);
    pacc0[6] = ffma2(sW2[t*8+6], a3.x, pacc0[6]);  pacc1[6] = ffma2(sW2[t*8+6], b3.x, pacc1[6]);
    pacc0[7] = ffma2(sW2[t*8+7], a3.y, pacc0[7]);  pacc1[7] = ffma2(sW2[t*8+7], b3.y, pacc1[7]);
  }

  float2 ls = unpack2(lsum2);
  float rA = 1.0f / ls.x, rB = 1.0f / ls.y;
  ull rA2 = pack2(rA, rA), rB2 = pack2(rB, rB);
  ulonglong2* opA = (ulonglong2*)(out + orow0);
  ulonglong2* opB = (ulonglong2*)(out + orow1);
  #pragma unroll
  for (int i = 0; i < 4; i++){
    ulonglong2 oa, ob;
    oa.x = ffma2(accA[2*i],   rA2, pacc0[2*i]);
    oa.y = ffma2(accA[2*i+1], rA2, pacc0[2*i+1]);
    ob.x = ffma2(accB[2*i],   rB2, pacc1[2*i]);
    ob.y = ffma2(accB[2*i+1], rB2, pacc1[2*i+1]);
    opA[i] = oa;
    opB[i] = ob;
  }
}

// ---------------------------------------------------------------------------
extern "C" void kernel_launch(void* const* d_in, const int* in_sizes, int n_in,
                              void* d_out, int out_size){
  const float* q    = (const float*)d_in[0];
  const float* k    = (const float*)d_in[1];
  const float* v    = (const float*)d_in[2];
  const float* p1w  = (const float*)d_in[3];
  const float* p1b  = (const float*)d_in[4];
  const float* bng  = (const float*)d_in[5];
  const float* bnb  = (const float*)d_in[6];
  const float* bnm  = (const float*)d_in[7];
  const float* bnv  = (const float*)d_in[8];
  const float* p2w  = (const float*)d_in[9];
  const float* p2b  = (const float*)d_in[10];
  const float* dynw = (const float*)d_in[11];
  const float* dynb = (const float*)d_in[12];
  float* out = (float*)d_out;

  cudaFuncSetAttribute(proj_kernel, cudaFuncAttributeMaxDynamicSharedMemorySize, 90112);
  cudaFuncSetAttribute(attn_kernel, cudaFuncAttributeMaxDynamicSharedMemorySize, 57344);

  pool_kernel<<<dim3(9, BB, 2), 256>>>(v);
  proj_kernel<<<BB, 256, 88320>>>(p1w, p1b, bng, bnb, bnm, bnv, p2w, p2b, dynw, dynb);
  attn_kernel<<<dim3(NHH, NWIN, BB), 192, 57280>>>(q, k, v, out);
}

// round 4
// speedup vs baseline: 2.8657x; 1.9835x over previous
#include <cuda_runtime.h>
#include <cuda_bf16.h>
#include <cstdint>

#define BB 16
#define HH 48
#define WWD 48
#define CC 128
#define NHH 8
#define SSW 8
#define LL (HH*WWD)
#define HD (CC/NHH)          // 16
#define NWIN (WWD/SSW)       // 6
#define SEQ (HH*SSW)         // 384

// scratch (no allocations allowed)
__device__ float g_pooled[BB*9*CC];
__device__ float g_w[BB*CC*9];
__device__ float g_bias[BB*CC];

typedef unsigned long long ull;
typedef unsigned int u32;

__device__ __forceinline__ ull ffma2(ull a, ull b, ull c){
  ull d; asm("fma.rn.f32x2 %0,%1,%2,%3;" : "=l"(d) : "l"(a), "l"(b), "l"(c)); return d;
}
__device__ __forceinline__ float2 unpack2(ull a){
  float2 r; asm("mov.b64 {%0,%1},%2;" : "=f"(r.x), "=f"(r.y) : "l"(a)); return r;
}
__device__ __forceinline__ float ex2f(float x){
  float r; asm("ex2.approx.ftz.f32 %0,%1;" : "=f"(r) : "f"(x)); return r;
}
// pack {lo=bf16(x), hi=bf16(y)}
__device__ __forceinline__ u32 cvt_bf2(float x, float y){
  u32 d; asm("cvt.rn.bf16x2.f32 %0,%1,%2;" : "=r"(d) : "f"(y), "f"(x)); return d;
}
// split two f32 into hi-bf16x2 and lo-bf16x2 (x -> slot lo, y -> slot hi)
__device__ __forceinline__ void split2(float x, float y, u32& hi, u32& lo){
  hi = cvt_bf2(x, y);
  float xf = __uint_as_float(hi << 16);
  float yf = __uint_as_float(hi & 0xffff0000u);
  lo = cvt_bf2(x - xf, y - yf);
}
__device__ __forceinline__ void mma_bf16(float (&d)[4], const u32 (&a)[4], const u32 (&b)[2]){
  asm volatile("mma.sync.aligned.m16n8k16.row.col.f32.bf16.bf16.f32 "
    "{%0,%1,%2,%3}, {%4,%5,%6,%7}, {%8,%9}, {%0,%1,%2,%3};"
    : "+f"(d[0]), "+f"(d[1]), "+f"(d[2]), "+f"(d[3])
    : "r"(a[0]), "r"(a[1]), "r"(a[2]), "r"(a[3]), "r"(b[0]), "r"(b[1]));
}

// ---------------------------------------------------------------------------
// Kernel 1: adaptive avg pool to 3x3 (uniform 16x16 block means)
// ---------------------------------------------------------------------------
__global__ void pool_kernel(const float* __restrict__ v){
  const int bin = blockIdx.x, b = blockIdx.y, ch = blockIdx.z;
  const int ky = bin / 3, kx = bin - ky*3;
  const int tid = threadIdx.x;
  const int c4 = tid & 15, part = tid >> 4;
  const int cg = ch*16 + c4;
  const float4* vb = (const float4*)(v + (size_t)b*LL*CC);
  const int h = ky*16 + part;
  const float4* row = vb + (size_t)(h*WWD + kx*16)*(CC/4) + cg;
  float4 s = make_float4(0.f,0.f,0.f,0.f);
  #pragma unroll
  for (int ww = 0; ww < 16; ww++){
    float4 t = row[ww*(CC/4)];
    s.x += t.x; s.y += t.y; s.z += t.z; s.w += t.w;
  }
  __shared__ float4 red[256];
  red[tid] = s; __syncthreads();
  #pragma unroll
  for (int off = 128; off >= 16; off >>= 1){
    if (tid < off){
      float4 o = red[tid+off];
      s.x += o.x; s.y += o.y; s.z += o.z; s.w += o.w;
      red[tid] = s;
    }
    __syncthreads();
  }
  if (tid < 16){
    s.x *= (1.f/256.f); s.y *= (1.f/256.f); s.z *= (1.f/256.f); s.w *= (1.f/256.f);
    ((float4*)g_pooled)[(b*9 + bin)*32 + ch*16 + tid] = s;
  }
}

// ---------------------------------------------------------------------------
// Kernel 2: proj1 -> BN -> GELU -> proj2 -> softmax over G -> dyn w / bias
// ---------------------------------------------------------------------------
__global__ void proj_kernel(const float* __restrict__ p1w, const float* __restrict__ p1b,
                            const float* __restrict__ bng, const float* __restrict__ bnb,
                            const float* __restrict__ bnm, const float* __restrict__ bnv,
                            const float* __restrict__ p2w, const float* __restrict__ p2b,
                            const float* __restrict__ dynw, const float* __restrict__ dynb){
  const int b = blockIdx.x, tid = threadIdx.x;
  extern __shared__ float ps[];
  float* pp  = ps;             // 10*128
  float* act = pp + 1280;      // 10*32
  float* p1t = act + 320;      // [c][o]
  float* w2t = p1t + 4096;     // [o][oc]

  for (int i = tid; i < 9*CC; i += 256) pp[i] = g_pooled[b*9*CC + i];
  for (int i = tid; i < 4096; i += 256){ int o = i >> 7, c = i & 127; p1t[c*32+o] = p1w[i]; }
  for (int i = tid; i < 16384; i += 256){ int oc = i >> 5, o = i & 31; w2t[o*512+oc] = p2w[i]; }
  __syncthreads();
  if (tid < 128){
    float s = 0.f;
    #pragma unroll
    for (int qq = 0; qq < 9; qq++) s += pp[qq*CC + tid];
    pp[9*CC + tid] = s * (1.f/9.f);
  }
  __syncthreads();

  for (int t = tid; t < 320; t += 256){
    int pos = t >> 5, o = t & 31;
    float s = p1b[o];
    const float* prow = pp + pos*CC;
    #pragma unroll 8
    for (int cc = 0; cc < CC; cc++) s += p1t[cc*32+o] * prow[cc];
    float inv = rsqrtf(bnv[o] + 1e-5f);
    s = (s - bnm[o]) * (inv * bng[o]) + bnb[o];
    s = 0.5f * s * (1.f + erff(s * 0.70710678118654752f));
    act[pos*32+o] = s;
  }
  __syncthreads();

  for (int t = tid; t < 1280; t += 256){
    int pos = t >> 7, c = t & 127;
    float y[4];
    #pragma unroll
    for (int g = 0; g < 4; g++){
      int oc = g*CC + c;
      float s = p2b[oc];
      #pragma unroll
      for (int o = 0; o < 32; o++) s += w2t[o*512+oc] * act[pos*32+o];
      y[g] = s;
    }
    float m = fmaxf(fmaxf(y[0],y[1]), fmaxf(y[2],y[3]));
    float e0 = expf(y[0]-m), e1 = expf(y[1]-m), e2 = expf(y[2]-m), e3 = expf(y[3]-m);
    float rs = 1.f / (e0+e1+e2+e3);
    if (pos < 9){
      float wv = e0*dynw[(0*CC+c)*9+pos] + e1*dynw[(1*CC+c)*9+pos]
               + e2*dynw[(2*CC+c)*9+pos] + e3*dynw[(3*CC+c)*9+pos];
      g_w[(b*CC + c)*9 + pos] = wv * rs;
    } else {
      float bv = e0*dynb[0*CC+c] + e1*dynb[1*CC+c] + e2*dynb[2*CC+c] + e3*dynb[3*CC+c];
      g_bias[b*CC + c] = bv * rs;
    }
  }
}

// ---------------------------------------------------------------------------
// Kernel 3: tensor-core attention (mma.sync bf16 3-term split) + fused conv
// grid (8 heads, 6 wblks, 32 b*half), 128 threads = 4 warps x 48 queries
// ---------------------------------------------------------------------------
#define KHI_OFF   0
#define KLO_OFF   12288
#define VTHI_OFF  24576
#define VTLO_OFF  36992
#define HALO_OFF  49408
#define W2_OFF    66048
#define B2_OFF    66624
#define SMEM_SZ   66688
#define VT_STRIDE 388      // bf16 elements per Vt row (padded)

__global__ void __launch_bounds__(128, 3)
attn_kernel(const float* __restrict__ q, const float* __restrict__ k,
            const float* __restrict__ v, float* __restrict__ out){
  extern __shared__ char smem[];
  char* sKhi = smem + KHI_OFF;       // [384 keys][16 bf16] row 32B
  char* sKlo = smem + KLO_OFF;
  char* sVthi = smem + VTHI_OFF;     // [16 ch][388 bf16]
  char* sVtlo = smem + VTLO_OFF;
  float* halo = (float*)(smem + HALO_OFF);  // [26][10][16] f32
  ull* sW2 = (ull*)(smem + W2_OFF);  // [9][8]
  ull* sB2 = (ull*)(smem + B2_OFF);  // [8]

  const int head = blockIdx.x, wblk = blockIdx.y;
  const int b = blockIdx.z >> 1, half = blockIdx.z & 1;
  const int c0 = head*HD;
  const int wb0 = wblk*SSW;
  const int tid = threadIdx.x;
  const int wid = tid >> 5, lane = tid & 31;
  const int grp = lane >> 2, tig = lane & 3;
  const size_t bbase = (size_t)b*LL*CC;

  // ---- fill K tiles (hi/lo bf16) ----
  for (int i = tid; i < SEQ*4; i += 128){
    int key = i >> 2, dq = (i & 3)*4;
    int hj = key >> 3, wj = key & 7;
    float4 kv = *(const float4*)(k + bbase + (size_t)(hj*WWD + wb0 + wj)*CC + c0 + dq);
    u32 h0,l0,h1,l1;
    split2(kv.x, kv.y, h0, l0);
    split2(kv.z, kv.w, h1, l1);
    u32* ph = (u32*)(sKhi + key*32 + dq*2);
    u32* pl = (u32*)(sKlo + key*32 + dq*2);
    ph[0]=h0; ph[1]=h1; pl[0]=l0; pl[1]=l1;
  }
  // ---- fill Vt tiles (transposed, hi/lo bf16) ----
  for (int i = tid; i < SEQ*4; i += 128){
    int key = i >> 2, dq = (i & 3)*4;
    int hj = key >> 3, wj = key & 7;
    float4 vv = *(const float4*)(v + bbase + (size_t)(hj*WWD + wb0 + wj)*CC + c0 + dq);
    float vals[4] = {vv.x, vv.y, vv.z, vv.w};
    #pragma unroll
    for (int d = 0; d < 4; d++){
      float x = vals[d];
      __nv_bfloat16 hb = __float2bfloat16(x);
      float lof = x - __bfloat162float(hb);
      ((__nv_bfloat16*)sVthi)[(dq+d)*VT_STRIDE + key] = hb;
      ((__nv_bfloat16*)sVtlo)[(dq+d)*VT_STRIDE + key] = __float2bfloat16(lof);
    }
  }
  // ---- fill fp32 halo tile for conv: rows half*24-1 .. half*24+24 ----
  for (int i = tid; i < 26*10*4; i += 128){
    int pos = i >> 2, dq = i & 3;
    int hh = pos / 10, ww = pos - hh*10;
    int gh = half*24 + hh - 1, gw = wb0 + ww - 1;
    float4 val = make_float4(0.f,0.f,0.f,0.f);
    if (gh >= 0 && gh < HH && gw >= 0 && gw < WWD)
      val = *(const float4*)(v + bbase + (size_t)(gh*WWD + gw)*CC + c0 + dq*4);
    ((float4*)halo)[pos*4 + dq] = val;
  }
  if (tid < 72){
    int t = tid >> 3, i = tid & 7;
    float2 wp = make_float2(g_w[(b*CC + c0 + 2*i)*9 + t], g_w[(b*CC + c0 + 2*i+1)*9 + t]);
    sW2[t*8+i] = *(ull*)&wp;
  }
  if (tid < 8){
    float2 bp = make_float2(g_bias[b*CC + c0 + 2*tid], g_bias[b*CC + c0 + 2*tid+1]);
    sB2[tid] = *(ull*)&bp;
  }

  // ---- Q fragments (scaled, split hi/lo) from gmem ----
  const float SCL = 0.36067376022224085f;  // 0.25 * log2(e)
  u32 ahi[3][4], alo[3][4];
  #pragma unroll
  for (int mf = 0; mf < 3; mf++){
    #pragma unroll
    for (int rs = 0; rs < 2; rs++){
      int m = wid*48 + mf*16 + grp + rs*8;     // query 0..191
      int hl = m >> 3, w = m & 7;
      const float* qr = q + bbase + (size_t)((half*24+hl)*WWD + wb0 + w)*CC + c0;
      float2 qa = *(const float2*)(qr + 2*tig);
      float2 qb = *(const float2*)(qr + 2*tig + 8);
      split2(qa.x*SCL, qa.y*SCL, ahi[mf][rs],   alo[mf][rs]);
      split2(qb.x*SCL, qb.y*SCL, ahi[mf][rs+2], alo[mf][rs+2]);
    }
  }
  __syncthreads();

  float o[3][2][4];
  #pragma unroll
  for (int mf = 0; mf < 3; mf++)
    #pragma unroll
    for (int cn = 0; cn < 2; cn++)
      #pragma unroll
      for (int r = 0; r < 4; r++) o[mf][cn][r] = 0.f;
  float ls[3][2];
  #pragma unroll
  for (int mf = 0; mf < 3; mf++){ ls[mf][0] = 0.f; ls[mf][1] = 0.f; }

  for (int kb = 0; kb < 12; kb++){
    const int kbase = kb*32;
    // B fragments for QK (4 n-frags of 8 keys each)
    u32 bh[4][2], bl[4][2];
    #pragma unroll
    for (int nf = 0; nf < 4; nf++){
      int key = kbase + nf*8 + grp;
      bh[nf][0] = *(const u32*)(sKhi + key*32 + tig*4);
      bh[nf][1] = *(const u32*)(sKhi + key*32 + 16 + tig*4);
      bl[nf][0] = *(const u32*)(sKlo + key*32 + tig*4);
      bl[nf][1] = *(const u32*)(sKlo + key*32 + 16 + tig*4);
    }
    float s[3][4][4];
    #pragma unroll
    for (int mf = 0; mf < 3; mf++)
      #pragma unroll
      for (int nf = 0; nf < 4; nf++){
        #pragma unroll
        for (int r = 0; r < 4; r++) s[mf][nf][r] = 0.f;
        mma_bf16(s[mf][nf], ahi[mf], bh[nf]);
        mma_bf16(s[mf][nf], ahi[mf], bl[nf]);
        mma_bf16(s[mf][nf], alo[mf], bh[nf]);
      }
    // softmax exp (scores bounded; no max pass) + lsum
    #pragma unroll
    for (int mf = 0; mf < 3; mf++){
      float la = 0.f, lb = 0.f;
      #pragma unroll
      for (int nf = 0; nf < 4; nf++){
        s[mf][nf][0] = ex2f(s[mf][nf][0]);
        s[mf][nf][1] = ex2f(s[mf][nf][1]);
        s[mf][nf][2] = ex2f(s[mf][nf][2]);
        s[mf][nf][3] = ex2f(s[mf][nf][3]);
        la += s[mf][nf][0] + s[mf][nf][1];
        lb += s[mf][nf][2] + s[mf][nf][3];
      }
      ls[mf][0] += la; ls[mf][1] += lb;
    }
    // PV: 2 k-steps of 16 keys
    #pragma unroll
    for (int ks = 0; ks < 2; ks++){
      u32 vh[2][2], vl[2][2];
      #pragma unroll
      for (int cn = 0; cn < 2; cn++){
        int ch = cn*8 + grp;
        const char* base_h = sVthi + (ch*VT_STRIDE + kbase + ks*16 + tig*2)*2;
        const char* base_l = sVtlo + (ch*VT_STRIDE + kbase + ks*16 + tig*2)*2;
        vh[cn][0] = *(const u32*)(base_h);
        vh[cn][1] = *(const u32*)(base_h + 16);
        vl[cn][0] = *(const u32*)(base_l);
        vl[cn][1] = *(const u32*)(base_l + 16);
      }
      #pragma unroll
      for (int mf = 0; mf < 3; mf++){
        u32 ph[4], pl[4];
        split2(s[mf][2*ks][0],   s[mf][2*ks][1],   ph[0], pl[0]);
        split2(s[mf][2*ks][2],   s[mf][2*ks][3],   ph[1], pl[1]);
        split2(s[mf][2*ks+1][0], s[mf][2*ks+1][1], ph[2], pl[2]);
        split2(s[mf][2*ks+1][2], s[mf][2*ks+1][3], ph[3], pl[3]);
        #pragma unroll
        for (int cn = 0; cn < 2; cn++){
          mma_bf16(o[mf][cn], ph, vh[cn]);
          mma_bf16(o[mf][cn], ph, vl[cn]);
          mma_bf16(o[mf][cn], pl, vh[cn]);
        }
      }
    }
  }

  // reduce lsum across the 4 threads of each row group
  #pragma unroll
  for (int mf = 0; mf < 3; mf++){
    #pragma unroll
    for (int rs = 0; rs < 2; rs++){
      float r = ls[mf][rs];
      r += __shfl_xor_sync(0xffffffffu, r, 1);
      r += __shfl_xor_sync(0xffffffffu, r, 2);
      ls[mf][rs] = 1.0f / r;
    }
  }

  // ---- epilogue: conv + bias + normalize + store ----
  #pragma unroll
  for (int mf = 0; mf < 3; mf++){
    #pragma unroll
    for (int rs = 0; rs < 2; rs++){
      int m = wid*48 + mf*16 + grp + rs*8;
      int hl = m >> 3, w = m & 7;
      float rinv = ls[mf][rs];
      float* orow = out + bbase + (size_t)((half*24+hl)*WWD + wb0 + w)*CC + c0;
      #pragma unroll
      for (int cn = 0; cn < 2; cn++){
        int cp = cn*4 + tig;     // channel pair index
        ull acc = sB2[cp];
        #pragma unroll
        for (int t = 0; t < 9; t++){
          int dy = t/3, dx = t - dy*3;
          ull vp = *(const ull*)(halo + ((hl+dy)*10 + (w+dx))*16 + cp*2);
          acc = ffma2(sW2[t*8+cp], vp, acc);
        }
        float2 cv = unpack2(acc);
        float2 res;
        res.x = o[mf][cn][rs*2]   * rinv + cv.x;
        res.y = o[mf][cn][rs*2+1] * rinv + cv.y;
        *(float2*)(orow + cn*8 + 2*tig) = res;
      }
    }
  }
}

// ---------------------------------------------------------------------------
extern "C" void kernel_launch(void* const* d_in, const int* in_sizes, int n_in,
                              void* d_out, int out_size){
  const float* q    = (const float*)d_in[0];
  const float* k    = (const float*)d_in[1];
  const float* v    = (const float*)d_in[2];
  const float* p1w  = (const float*)d_in[3];
  const float* p1b  = (const float*)d_in[4];
  const float* bng  = (const float*)d_in[5];
  const float* bnb  = (const float*)d_in[6];
  const float* bnm  = (const float*)d_in[7];
  const float* bnv  = (const float*)d_in[8];
  const float* p2w  = (const float*)d_in[9];
  const float* p2b  = (const float*)d_in[10];
  const float* dynw = (const float*)d_in[11];
  const float* dynb = (const float*)d_in[12];
  float* out = (float*)d_out;

  cudaFuncSetAttribute(proj_kernel, cudaFuncAttributeMaxDynamicSharedMemorySize, 90112);
  cudaFuncSetAttribute(attn_kernel, cudaFuncAttributeMaxDynamicSharedMemorySize, SMEM_SZ);

  pool_kernel<<<dim3(9, BB, 2), 256>>>(v);
  proj_kernel<<<BB, 256, 88320>>>(p1w, p1b, bng, bnb, bnm, bnv, p2w, p2b, dynw, dynb);
  attn_kernel<<<dim3(NHH, NWIN, BB*2), 128, SMEM_SZ>>>(q, k, v, out);
}

// round 5
// speedup vs baseline: 3.2138x; 1.1214x over previous
#include <cuda_runtime.h>
#include <cuda_bf16.h>
#include <cstdint>

#define BB 16
#define HH 48
#define WWD 48
#define CC 128
#define NHH 8
#define SSW 8
#define LL (HH*WWD)
#define HD (CC/NHH)          // 16
#define NWIN (WWD/SSW)       // 6
#define SEQ (HH*SSW)         // 384

// scratch (no allocations allowed)
__device__ float g_pooled[BB*9*CC];
__device__ float g_w[BB*CC*9];
__device__ float g_bias[BB*CC];

typedef unsigned long long ull;
typedef unsigned int u32;

__device__ __forceinline__ ull ffma2(ull a, ull b, ull c){
  ull d; asm("fma.rn.f32x2 %0,%1,%2,%3;" : "=l"(d) : "l"(a), "l"(b), "l"(c)); return d;
}
__device__ __forceinline__ float2 unpack2(ull a){
  float2 r; asm("mov.b64 {%0,%1},%2;" : "=f"(r.x), "=f"(r.y) : "l"(a)); return r;
}
__device__ __forceinline__ float ex2f(float x){
  float r; asm("ex2.approx.ftz.f32 %0,%1;" : "=f"(r) : "f"(x)); return r;
}
// pack {lo=bf16(x), hi=bf16(y)}
__device__ __forceinline__ u32 cvt_bf2(float x, float y){
  u32 d; asm("cvt.rn.bf16x2.f32 %0,%1,%2;" : "=r"(d) : "f"(y), "f"(x)); return d;
}
// split two f32 into hi-bf16x2 and lo-bf16x2
__device__ __forceinline__ void split2(float x, float y, u32& hi, u32& lo){
  hi = cvt_bf2(x, y);
  float xf = __uint_as_float(hi << 16);
  float yf = __uint_as_float(hi & 0xffff0000u);
  lo = cvt_bf2(x - xf, y - yf);
}
__device__ __forceinline__ void mma_bf16(float (&d)[4], const u32 (&a)[4], u32 b0, u32 b1){
  asm volatile("mma.sync.aligned.m16n8k16.row.col.f32.bf16.bf16.f32 "
    "{%0,%1,%2,%3}, {%4,%5,%6,%7}, {%8,%9}, {%0,%1,%2,%3};"
    : "+f"(d[0]), "+f"(d[1]), "+f"(d[2]), "+f"(d[3])
    : "r"(a[0]), "r"(a[1]), "r"(a[2]), "r"(a[3]), "r"(b0), "r"(b1));
}

// ---------------------------------------------------------------------------
// Kernel 1: adaptive avg pool to 3x3 (uniform 16x16 block means)
// grid (9 bins, 16 batches, 4 ch quarters), 512 threads, 4 float4 loads each
// ---------------------------------------------------------------------------
__global__ void pool_kernel(const float* __restrict__ v){
  const int bin = blockIdx.x, b = blockIdx.y, ch = blockIdx.z;
  const int ky = bin / 3, kx = bin - ky*3;
  const int tid = threadIdx.x;
  const int c4 = tid & 7, part = tid >> 3;     // 8 ch-groups, 64 parts
  const int row = part >> 2, quad = part & 3;  // 16 rows x 4 col-quads
  const int cg = ch*8 + c4;
  const float4* vb = (const float4*)(v + (size_t)b*LL*CC);
  const int h = ky*16 + row;
  const float4* p = vb + (size_t)(h*WWD + kx*16 + quad*4)*(CC/4) + cg;
  float4 s = make_float4(0.f,0.f,0.f,0.f);
  #pragma unroll
  for (int ww = 0; ww < 4; ww++){
    float4 t = p[ww*(CC/4)];
    s.x += t.x; s.y += t.y; s.z += t.z; s.w += t.w;
  }
  __shared__ float4 red[512];
  red[tid] = s; __syncthreads();
  #pragma unroll
  for (int off = 256; off >= 8; off >>= 1){
    if (tid < off){
      float4 o = red[tid+off];
      s.x += o.x; s.y += o.y; s.z += o.z; s.w += o.w;
      red[tid] = s;
    }
    __syncthreads();
  }
  if (tid < 8){
    s.x *= (1.f/256.f); s.y *= (1.f/256.f); s.z *= (1.f/256.f); s.w *= (1.f/256.f);
    ((float4*)g_pooled)[(b*9 + bin)*32 + ch*8 + tid] = s;
  }
}

// ---------------------------------------------------------------------------
// Kernel 2: proj1 -> BN -> GELU -> proj2 -> softmax over G -> dyn w / bias
// ---------------------------------------------------------------------------
__global__ void proj_kernel(const float* __restrict__ p1w, const float* __restrict__ p1b,
                            const float* __restrict__ bng, const float* __restrict__ bnb,
                            const float* __restrict__ bnm, const float* __restrict__ bnv,
                            const float* __restrict__ p2w, const float* __restrict__ p2b,
                            const float* __restrict__ dynw, const float* __restrict__ dynb){
  const int b = blockIdx.x, tid = threadIdx.x;
  extern __shared__ float ps[];
  float* pp  = ps;             // 10*128
  float* act = pp + 1280;      // 10*32
  float* p1t = act + 320;      // [c][o]
  float* w2t = p1t + 4096;     // [o][oc]

  for (int i = tid; i < 9*CC; i += 256) pp[i] = g_pooled[b*9*CC + i];
  for (int i = tid; i < 4096; i += 256){ int o = i >> 7, c = i & 127; p1t[c*32+o] = p1w[i]; }
  for (int i = tid; i < 16384; i += 256){ int oc = i >> 5, o = i & 31; w2t[o*512+oc] = p2w[i]; }
  __syncthreads();
  if (tid < 128){
    float s = 0.f;
    #pragma unroll
    for (int qq = 0; qq < 9; qq++) s += pp[qq*CC + tid];
    pp[9*CC + tid] = s * (1.f/9.f);
  }
  __syncthreads();

  for (int t = tid; t < 320; t += 256){
    int pos = t >> 5, o = t & 31;
    float s = p1b[o];
    const float* prow = pp + pos*CC;
    #pragma unroll 8
    for (int cc = 0; cc < CC; cc++) s += p1t[cc*32+o] * prow[cc];
    float inv = rsqrtf(bnv[o] + 1e-5f);
    s = (s - bnm[o]) * (inv * bng[o]) + bnb[o];
    s = 0.5f * s * (1.f + erff(s * 0.70710678118654752f));
    act[pos*32+o] = s;
  }
  __syncthreads();

  for (int t = tid; t < 1280; t += 256){
    int pos = t >> 7, c = t & 127;
    float y[4];
    #pragma unroll
    for (int g = 0; g < 4; g++){
      int oc = g*CC + c;
      float s = p2b[oc];
      #pragma unroll
      for (int o = 0; o < 32; o++) s += w2t[o*512+oc] * act[pos*32+o];
      y[g] = s;
    }
    float m = fmaxf(fmaxf(y[0],y[1]), fmaxf(y[2],y[3]));
    float e0 = expf(y[0]-m), e1 = expf(y[1]-m), e2 = expf(y[2]-m), e3 = expf(y[3]-m);
    float rs = 1.f / (e0+e1+e2+e3);
    if (pos < 9){
      float wv = e0*dynw[(0*CC+c)*9+pos] + e1*dynw[(1*CC+c)*9+pos]
               + e2*dynw[(2*CC+c)*9+pos] + e3*dynw[(3*CC+c)*9+pos];
      g_w[(b*CC + c)*9 + pos] = wv * rs;
    } else {
      float bv = e0*dynb[0*CC+c] + e1*dynb[1*CC+c] + e2*dynb[2*CC+c] + e3*dynb[3*CC+c];
      g_bias[b*CC + c] = bv * rs;
    }
  }
}

// ---------------------------------------------------------------------------
// Kernel 3: tensor-core attention (mma.sync bf16 3-term split) + fused conv
// grid (8 heads, 6 wblks, 16 batches), 256 threads = 8 warps x 48 queries
// Full window (384 queries) per CTA: K/V tiles loaded+split ONCE per window.
//
// K smem: per key a 96B row: [8 u32 hi, frag-permuted][8 u32 lo][32B pad]
//   frag order p(j) = (j&3)*2 + (j>>2)  -> thread reads uint2 (LDS.64)
// V smem: [16 ch][24 key-blocks x 64B], chunk t (16B) = keys {2t,2t+1,2t+8,2t+9}
//   as [hi 8B][lo 8B]  -> thread reads uint4 (LDS.128), ch stride 1600B
//   (conflict-free: (grp*1600 + tig*16) mod 128 distinct per 8-lane phase)
// ---------------------------------------------------------------------------
#define KOFF    0
#define KROW    96
#define VOFF    36864
#define VSTRIDE 1600
#define HOFF    62464
#define W2_OFF  94464
#define B2_OFF  95040
#define SMEM_SZ 95104

__global__ void __launch_bounds__(256, 2)
attn_kernel(const float* __restrict__ q, const float* __restrict__ k,
            const float* __restrict__ v, float* __restrict__ out){
  extern __shared__ char smem[];
  char* sK  = smem + KOFF;
  char* sVt = smem + VOFF;
  float* halo = (float*)(smem + HOFF);   // [50][10][16] f32
  ull* sW2 = (ull*)(smem + W2_OFF);      // [9][8]
  ull* sB2 = (ull*)(smem + B2_OFF);      // [8]

  const int head = blockIdx.x, wblk = blockIdx.y, b = blockIdx.z;
  const int c0 = head*HD;
  const int wb0 = wblk*SSW;
  const int tid = threadIdx.x;
  const int wid = tid >> 5, lane = tid & 31;
  const int grp = lane >> 2, tig = lane & 3;
  const size_t bbase = (size_t)b*LL*CC;

  // ---- fill K rows (hi/lo bf16, frag-permuted) ----
  for (int i = tid; i < SEQ*4; i += 256){
    int key = i >> 2, dq = (i & 3)*4;
    int hj = key >> 3, wj = key & 7;
    float4 kv = *(const float4*)(k + bbase + (size_t)(hj*WWD + wb0 + wj)*CC + c0 + dq);
    u32 h0,l0,h1,l1;
    split2(kv.x, kv.y, h0, l0);
    split2(kv.z, kv.w, h1, l1);
    int j0 = dq >> 1;
    int p0 = (j0 & 3)*2 + (j0 >> 2);
    int p1 = ((j0+1) & 3)*2 + ((j0+1) >> 2);
    u32* row = (u32*)(sK + key*KROW);
    row[p0] = h0; row[p1] = h1;
    row[8+p0] = l0; row[8+p1] = l1;
  }
  // ---- fill Vt (transposed, hi/lo interleaved per 4-key chunk) ----
  for (int i = tid; i < SEQ*4; i += 256){
    int key = i >> 2, dq = (i & 3)*4;
    int hj = key >> 3, wj = key & 7;
    float4 vv = *(const float4*)(v + bbase + (size_t)(hj*WWD + wb0 + wj)*CC + c0 + dq);
    float vals[4] = {vv.x, vv.y, vv.z, vv.w};
    int blk = key >> 4, r = key & 15;
    int chunk = (r & 7) >> 1;
    int idx = (r & 1) | ((r >> 3) << 1);
    char* base = sVt + blk*64 + chunk*16 + idx*2;
    #pragma unroll
    for (int d = 0; d < 4; d++){
      float x = vals[d];
      __nv_bfloat16 hb = __float2bfloat16(x);
      float lof = x - __bfloat162float(hb);
      char* rowp = base + (dq+d)*VSTRIDE;
      *(__nv_bfloat16*)(rowp)     = hb;
      *(__nv_bfloat16*)(rowp + 8) = __float2bfloat16(lof);
    }
  }
  // ---- fill fp32 halo for conv ----
  for (int i = tid; i < 50*10*4; i += 256){
    int pos = i >> 2, dq = i & 3;
    int hh = pos / 10, ww = pos - hh*10;
    int gh = hh - 1, gw = wb0 + ww - 1;
    float4 val = make_float4(0.f,0.f,0.f,0.f);
    if (gh >= 0 && gh < HH && gw >= 0 && gw < WWD)
      val = *(const float4*)(v + bbase + (size_t)(gh*WWD + gw)*CC + c0 + dq*4);
    ((float4*)halo)[pos*4 + dq] = val;
  }
  if (tid < 72){
    int t = tid >> 3, i = tid & 7;
    float2 wp = make_float2(g_w[(b*CC + c0 + 2*i)*9 + t], g_w[(b*CC + c0 + 2*i+1)*9 + t]);
    sW2[t*8+i] = *(ull*)&wp;
  }
  if (tid < 8){
    float2 bp = make_float2(g_bias[b*CC + c0 + 2*tid], g_bias[b*CC + c0 + 2*tid+1]);
    sB2[tid] = *(ull*)&bp;
  }

  // ---- Q fragments (scaled, split hi/lo) ----
  const float SCL = 0.36067376022224085f;  // 0.25 * log2(e)
  u32 ahi[3][4], alo[3][4];
  #pragma unroll
  for (int mf = 0; mf < 3; mf++){
    #pragma unroll
    for (int rs = 0; rs < 2; rs++){
      int m = wid*48 + mf*16 + grp + rs*8;     // query 0..383
      int hl = m >> 3, w = m & 7;
      const float* qr = q + bbase + (size_t)(hl*WWD + wb0 + w)*CC + c0;
      float2 qa = *(const float2*)(qr + 2*tig);
      float2 qb = *(const float2*)(qr + 2*tig + 8);
      split2(qa.x*SCL, qa.y*SCL, ahi[mf][rs],   alo[mf][rs]);
      split2(qb.x*SCL, qb.y*SCL, ahi[mf][rs+2], alo[mf][rs+2]);
    }
  }
  __syncthreads();

  float o[3][2][4];
  #pragma unroll
  for (int mf = 0; mf < 3; mf++)
    #pragma unroll
    for (int cn = 0; cn < 2; cn++)
      #pragma unroll
      for (int r = 0; r < 4; r++) o[mf][cn][r] = 0.f;
  float ls[3][2];
  #pragma unroll
  for (int mf = 0; mf < 3; mf++){ ls[mf][0] = 0.f; ls[mf][1] = 0.f; }

  for (int kt = 0; kt < 24; kt++){           // 16 keys per step
    const int kbase = kt*16;
    // K B-fragments for 2 n-frags (LDS.64 each)
    uint2 kh[2], kl[2];
    #pragma unroll
    for (int nf = 0; nf < 2; nf++){
      const char* base = sK + (kbase + nf*8 + grp)*KROW + tig*8;
      kh[nf] = *(const uint2*)(base);
      kl[nf] = *(const uint2*)(base + 32);
    }
    // S = Q*K^T (3-term split)
    float s[3][2][4];
    #pragma unroll
    for (int mf = 0; mf < 3; mf++)
      #pragma unroll
      for (int nf = 0; nf < 2; nf++){
        #pragma unroll
        for (int r = 0; r < 4; r++) s[mf][nf][r] = 0.f;
        mma_bf16(s[mf][nf], ahi[mf], kh[nf].x, kh[nf].y);
        mma_bf16(s[mf][nf], ahi[mf], kl[nf].x, kl[nf].y);
        mma_bf16(s[mf][nf], alo[mf], kh[nf].x, kh[nf].y);
      }
    // softmax exp (scores bounded; no max pass) + lsum
    #pragma unroll
    for (int mf = 0; mf < 3; mf++){
      float la = 0.f, lb = 0.f;
      #pragma unroll
      for (int nf = 0; nf < 2; nf++){
        s[mf][nf][0] = ex2f(s[mf][nf][0]);
        s[mf][nf][1] = ex2f(s[mf][nf][1]);
        s[mf][nf][2] = ex2f(s[mf][nf][2]);
        s[mf][nf][3] = ex2f(s[mf][nf][3]);
        la += s[mf][nf][0] + s[mf][nf][1];
        lb += s[mf][nf][2] + s[mf][nf][3];
      }
      ls[mf][0] += la; ls[mf][1] += lb;
    }
    // V B-fragments (one LDS.128 per cn: {vh0,vh1,vl0,vl1})
    uint4 vv[2];
    #pragma unroll
    for (int cn = 0; cn < 2; cn++){
      int ch = cn*8 + grp;
      vv[cn] = *(const uint4*)(sVt + ch*VSTRIDE + kt*64 + tig*16);
    }
    // O += P*V (3-term split)
    #pragma unroll
    for (int mf = 0; mf < 3; mf++){
      u32 ph[4], pl[4];
      split2(s[mf][0][0], s[mf][0][1], ph[0], pl[0]);
      split2(s[mf][0][2], s[mf][0][3], ph[1], pl[1]);
      split2(s[mf][1][0], s[mf][1][1], ph[2], pl[2]);
      split2(s[mf][1][2], s[mf][1][3], ph[3], pl[3]);
      #pragma unroll
      for (int cn = 0; cn < 2; cn++){
        mma_bf16(o[mf][cn], ph, vv[cn].x, vv[cn].y);
        mma_bf16(o[mf][cn], ph, vv[cn].z, vv[cn].w);
        mma_bf16(o[mf][cn], pl, vv[cn].x, vv[cn].y);
      }
    }
  }

  // reduce lsum across the 4 threads of each row group
  #pragma unroll
  for (int mf = 0; mf < 3; mf++){
    #pragma unroll
    for (int rs = 0; rs < 2; rs++){
      float r = ls[mf][rs];
      r += __shfl_xor_sync(0xffffffffu, r, 1);
      r += __shfl_xor_sync(0xffffffffu, r, 2);
      ls[mf][rs] = 1.0f / r;
    }
  }

  // ---- epilogue: conv + bias + normalize + store ----
  #pragma unroll
  for (int mf = 0; mf < 3; mf++){
    #pragma unroll
    for (int rs = 0; rs < 2; rs++){
      int m = wid*48 + mf*16 + grp + rs*8;
      int hl = m >> 3, w = m & 7;
      float rinv = ls[mf][rs];
      float* orow = out + bbase + (size_t)(hl*WWD + wb0 + w)*CC + c0;
      #pragma unroll
      for (int cn = 0; cn < 2; cn++){
        int cp = cn*4 + tig;     // channel pair index
        ull acc = sB2[cp];
        #pragma unroll
        for (int t = 0; t < 9; t++){
          int dy = t/3, dx = t - dy*3;
          ull vp = *(const ull*)(halo + ((hl+dy)*10 + (w+dx))*16 + cp*2);
          acc = ffma2(sW2[t*8+cp], vp, acc);
        }
        float2 cv = unpack2(acc);
        float2 res;
        res.x = o[mf][cn][rs*2]   * rinv + cv.x;
        res.y = o[mf][cn][rs*2+1] * rinv + cv.y;
        *(float2*)(orow + cn*8 + 2*tig) = res;
      }
    }
  }
}

// ---------------------------------------------------------------------------
extern "C" void kernel_launch(void* const* d_in, const int* in_sizes, int n_in,
                              void* d_out, int out_size){
  const float* q    = (const float*)d_in[0];
  const float* k    = (const float*)d_in[1];
  const float* v    = (const float*)d_in[2];
  const float* p1w  = (const float*)d_in[3];
  const float* p1b  = (const float*)d_in[4];
  const float* bng  = (const float*)d_in[5];
  const float* bnb  = (const float*)d_in[6];
  const float* bnm  = (const float*)d_in[7];
  const float* bnv  = (const float*)d_in[8];
  const float* p2w  = (const float*)d_in[9];
  const float* p2b  = (const float*)d_in[10];
  const float* dynw = (const float*)d_in[11];
  const float* dynb = (const float*)d_in[12];
  float* out = (float*)d_out;

  cudaFuncSetAttribute(proj_kernel, cudaFuncAttributeMaxDynamicSharedMemorySize, 90112);
  cudaFuncSetAttribute(attn_kernel, cudaFuncAttributeMaxDynamicSharedMemorySize, SMEM_SZ);

  pool_kernel<<<dim3(9, BB, 4), 512>>>(v);
  proj_kernel<<<BB, 256, 88320>>>(p1w, p1b, bng, bnb, bnm, bnv, p2w, p2b, dynw, dynb);
  attn_kernel<<<dim3(NHH, NWIN, BB), 256, SMEM_SZ>>>(q, k, v, out);
}

// round 6
// speedup vs baseline: 4.4408x; 1.3818x over previous
#include <cuda_runtime.h>
#include <cuda_bf16.h>
#include <cuda_fp16.h>
#include <cstdint>

#define BB 16
#define HH 48
#define WWD 48
#define CC 128
#define NHH 8
#define SSW 8
#define LL (HH*WWD)
#define HD (CC/NHH)          // 16
#define NWIN (WWD/SSW)       // 6
#define SEQ (HH*SSW)         // 384

// scratch (no allocations allowed)
__device__ float g_pooled[BB*9*CC];
__device__ float g_w[BB*CC*9];
__device__ float g_bias[BB*CC];

typedef unsigned long long ull;
typedef unsigned int u32;

__device__ __forceinline__ ull ffma2(ull a, ull b, ull c){
  ull d; asm("fma.rn.f32x2 %0,%1,%2,%3;" : "=l"(d) : "l"(a), "l"(b), "l"(c)); return d;
}
__device__ __forceinline__ float2 unpack2(ull a){
  float2 r; asm("mov.b64 {%0,%1},%2;" : "=f"(r.x), "=f"(r.y) : "l"(a)); return r;
}
__device__ __forceinline__ float ex2f(float x){
  float r; asm("ex2.approx.ftz.f32 %0,%1;" : "=f"(r) : "f"(x)); return r;
}
// pack {lo=f16(x), hi=f16(y)}
__device__ __forceinline__ u32 cvt_h2(float x, float y){
  u32 d; asm("cvt.rn.f16x2.f32 %0,%1,%2;" : "=r"(d) : "f"(y), "f"(x)); return d;
}
__device__ __forceinline__ void mma_f16(float (&d)[4], const u32 (&a)[4], u32 b0, u32 b1){
  asm volatile("mma.sync.aligned.m16n8k16.row.col.f32.f16.f16.f32 "
    "{%0,%1,%2,%3}, {%4,%5,%6,%7}, {%8,%9}, {%0,%1,%2,%3};"
    : "+f"(d[0]), "+f"(d[1]), "+f"(d[2]), "+f"(d[3])
    : "r"(a[0]), "r"(a[1]), "r"(a[2]), "r"(a[3]), "r"(b0), "r"(b1));
}

// ---------------------------------------------------------------------------
// Kernel 1: adaptive avg pool to 3x3 (uniform 16x16 block means)
// ---------------------------------------------------------------------------
__global__ void pool_kernel(const float* __restrict__ v){
  const int bin = blockIdx.x, b = blockIdx.y, ch = blockIdx.z;
  const int ky = bin / 3, kx = bin - ky*3;
  const int tid = threadIdx.x;
  const int c4 = tid & 7, part = tid >> 3;
  const int row = part >> 2, quad = part & 3;
  const int cg = ch*8 + c4;
  const float4* vb = (const float4*)(v + (size_t)b*LL*CC);
  const int h = ky*16 + row;
  const float4* p = vb + (size_t)(h*WWD + kx*16 + quad*4)*(CC/4) + cg;
  float4 s = make_float4(0.f,0.f,0.f,0.f);
  #pragma unroll
  for (int ww = 0; ww < 4; ww++){
    float4 t = p[ww*(CC/4)];
    s.x += t.x; s.y += t.y; s.z += t.z; s.w += t.w;
  }
  __shared__ float4 red[512];
  red[tid] = s; __syncthreads();
  #pragma unroll
  for (int off = 256; off >= 8; off >>= 1){
    if (tid < off){
      float4 o = red[tid+off];
      s.x += o.x; s.y += o.y; s.z += o.z; s.w += o.w;
      red[tid] = s;
    }
    __syncthreads();
  }
  if (tid < 8){
    s.x *= (1.f/256.f); s.y *= (1.f/256.f); s.z *= (1.f/256.f); s.w *= (1.f/256.f);
    ((float4*)g_pooled)[(b*9 + bin)*32 + ch*8 + tid] = s;
  }
}

// ---------------------------------------------------------------------------
// Kernel 2: proj1 -> BN -> GELU -> proj2 -> softmax over G -> dyn w / bias
// ---------------------------------------------------------------------------
__global__ void proj_kernel(const float* __restrict__ p1w, const float* __restrict__ p1b,
                            const float* __restrict__ bng, const float* __restrict__ bnb,
                            const float* __restrict__ bnm, const float* __restrict__ bnv,
                            const float* __restrict__ p2w, const float* __restrict__ p2b,
                            const float* __restrict__ dynw, const float* __restrict__ dynb){
  const int b = blockIdx.x, tid = threadIdx.x;
  extern __shared__ float ps[];
  float* pp  = ps;             // 10*128
  float* act = pp + 1280;      // 10*32
  float* p1t = act + 320;      // [c][o]
  float* w2t = p1t + 4096;     // [o][oc]

  for (int i = tid; i < 9*CC; i += 256) pp[i] = g_pooled[b*9*CC + i];
  for (int i = tid; i < 4096; i += 256){ int o = i >> 7, c = i & 127; p1t[c*32+o] = p1w[i]; }
  for (int i = tid; i < 16384; i += 256){ int oc = i >> 5, o = i & 31; w2t[o*512+oc] = p2w[i]; }
  __syncthreads();
  if (tid < 128){
    float s = 0.f;
    #pragma unroll
    for (int qq = 0; qq < 9; qq++) s += pp[qq*CC + tid];
    pp[9*CC + tid] = s * (1.f/9.f);
  }
  __syncthreads();

  for (int t = tid; t < 320; t += 256){
    int pos = t >> 5, o = t & 31;
    float s = p1b[o];
    const float* prow = pp + pos*CC;
    #pragma unroll 8
    for (int cc = 0; cc < CC; cc++) s += p1t[cc*32+o] * prow[cc];
    float inv = rsqrtf(bnv[o] + 1e-5f);
    s = (s - bnm[o]) * (inv * bng[o]) + bnb[o];
    s = 0.5f * s * (1.f + erff(s * 0.70710678118654752f));
    act[pos*32+o] = s;
  }
  __syncthreads();

  for (int t = tid; t < 1280; t += 256){
    int pos = t >> 7, c = t & 127;
    float y[4];
    #pragma unroll
    for (int g = 0; g < 4; g++){
      int oc = g*CC + c;
      float s = p2b[oc];
      #pragma unroll
      for (int o = 0; o < 32; o++) s += w2t[o*512+oc] * act[pos*32+o];
      y[g] = s;
    }
    float m = fmaxf(fmaxf(y[0],y[1]), fmaxf(y[2],y[3]));
    float e0 = expf(y[0]-m), e1 = expf(y[1]-m), e2 = expf(y[2]-m), e3 = expf(y[3]-m);
    float rs = 1.f / (e0+e1+e2+e3);
    if (pos < 9){
      float wv = e0*dynw[(0*CC+c)*9+pos] + e1*dynw[(1*CC+c)*9+pos]
               + e2*dynw[(2*CC+c)*9+pos] + e3*dynw[(3*CC+c)*9+pos];
      g_w[(b*CC + c)*9 + pos] = wv * rs;
    } else {
      float bv = e0*dynb[0*CC+c] + e1*dynb[1*CC+c] + e2*dynb[2*CC+c] + e3*dynb[3*CC+c];
      g_bias[b*CC + c] = bv * rs;
    }
  }
}

// ---------------------------------------------------------------------------
// Kernel 3: tensor-core attention, SINGLE fp16 mma per GEMM term + fused conv
// grid (8 heads, 6 wblks, 16 batches), 256 threads = 8 warps x 48 queries
//
// K smem: per key 32B = 8 u32 fp16x2, slot s: s=2t -> ch{2t,2t+1}, s=2t+1 ->
//   ch{2t+8,2t+9}; lane(grp,tig) reads uint2 at key*32+tig*8 (conflict-free).
// V smem: [16 ch][24 blocks x 32B], within block slot 2t = keys{2t,2t+1},
//   slot 2t+1 = keys{2t+8,2t+9}; ch stride 800B (conflict-free phases).
// Softmax stats stay fp32 (ex2 + lsum + normalize).
// ---------------------------------------------------------------------------
#define KOFF    0
#define VOFF    12288
#define VSTRIDE 800
#define HOFF    25088
#define W2_OFF  57088
#define B2_OFF  57664
#define SMEM_SZ 57728

__global__ void __launch_bounds__(256, 2)
attn_kernel(const float* __restrict__ q, const float* __restrict__ k,
            const float* __restrict__ v, float* __restrict__ out){
  extern __shared__ char smem[];
  char* sK  = smem + KOFF;
  char* sVt = smem + VOFF;
  float* halo = (float*)(smem + HOFF);   // [50][10][16] f32
  ull* sW2 = (ull*)(smem + W2_OFF);      // [9][8]
  ull* sB2 = (ull*)(smem + B2_OFF);      // [8]

  const int head = blockIdx.x, wblk = blockIdx.y, b = blockIdx.z;
  const int c0 = head*HD;
  const int wb0 = wblk*SSW;
  const int tid = threadIdx.x;
  const int wid = tid >> 5, lane = tid & 31;
  const int grp = lane >> 2, tig = lane & 3;
  const size_t bbase = (size_t)b*LL*CC;

  // ---- fill K (fp16, slot-permuted) ----
  for (int i = tid; i < SEQ*4; i += 256){
    int key = i >> 2, dq = (i & 3)*4;
    int hj = key >> 3, wj = key & 7;
    float4 kv = *(const float4*)(k + bbase + (size_t)(hj*WWD + wb0 + wj)*CC + c0 + dq);
    int j0 = dq >> 1;                         // pair index 0,2,4,6
    int s0 = (j0 < 4) ? 2*j0 : 2*j0 - 7;
    int s1 = (j0+1 < 4) ? 2*(j0+1) : 2*(j0+1) - 7;
    u32* row = (u32*)(sK + key*32);
    row[s0] = cvt_h2(kv.x, kv.y);
    row[s1] = cvt_h2(kv.z, kv.w);
  }
  // ---- fill Vt (fp16 transposed, slot-permuted per 16-key block) ----
  for (int i = tid; i < SEQ*4; i += 256){
    int key = i >> 2, dq = (i & 3)*4;
    int hj = key >> 3, wj = key & 7;
    float4 vv = *(const float4*)(v + bbase + (size_t)(hj*WWD + wb0 + wj)*CC + c0 + dq);
    float vals[4] = {vv.x, vv.y, vv.z, vv.w};
    int blk = key >> 4, r = key & 15;
    int pr = r >> 1;
    int slot = (r < 8) ? 2*pr : 2*(pr-4)+1;
    int byte = blk*32 + slot*4 + (r & 1)*2;
    #pragma unroll
    for (int d = 0; d < 4; d++)
      *(__half*)(sVt + (dq+d)*VSTRIDE + byte) = __float2half(vals[d]);
  }
  // ---- fill fp32 halo for conv ----
  for (int i = tid; i < 50*10*4; i += 256){
    int pos = i >> 2, dq = i & 3;
    int hh = pos / 10, ww = pos - hh*10;
    int gh = hh - 1, gw = wb0 + ww - 1;
    float4 val = make_float4(0.f,0.f,0.f,0.f);
    if (gh >= 0 && gh < HH && gw >= 0 && gw < WWD)
      val = *(const float4*)(v + bbase + (size_t)(gh*WWD + gw)*CC + c0 + dq*4);
    ((float4*)halo)[pos*4 + dq] = val;
  }
  if (tid < 72){
    int t = tid >> 3, i = tid & 7;
    float2 wp = make_float2(g_w[(b*CC + c0 + 2*i)*9 + t], g_w[(b*CC + c0 + 2*i+1)*9 + t]);
    sW2[t*8+i] = *(ull*)&wp;
  }
  if (tid < 8){
    float2 bp = make_float2(g_bias[b*CC + c0 + 2*tid], g_bias[b*CC + c0 + 2*tid+1]);
    sB2[tid] = *(ull*)&bp;
  }

  // ---- Q fragments (scaled fp16) ----
  const float SCL = 0.36067376022224085f;  // 0.25 * log2(e)
  u32 aq[3][4];
  #pragma unroll
  for (int mf = 0; mf < 3; mf++){
    #pragma unroll
    for (int rs = 0; rs < 2; rs++){
      int m = wid*48 + mf*16 + grp + rs*8;     // query 0..383
      int hl = m >> 3, w = m & 7;
      const float* qr = q + bbase + (size_t)(hl*WWD + wb0 + w)*CC + c0;
      float2 qa = *(const float2*)(qr + 2*tig);
      float2 qb = *(const float2*)(qr + 2*tig + 8);
      aq[mf][rs]   = cvt_h2(qa.x*SCL, qa.y*SCL);
      aq[mf][rs+2] = cvt_h2(qb.x*SCL, qb.y*SCL);
    }
  }
  __syncthreads();

  float o[3][2][4];
  #pragma unroll
  for (int mf = 0; mf < 3; mf++)
    #pragma unroll
    for (int cn = 0; cn < 2; cn++)
      #pragma unroll
      for (int r = 0; r < 4; r++) o[mf][cn][r] = 0.f;
  float ls[3][2];
  #pragma unroll
  for (int mf = 0; mf < 3; mf++){ ls[mf][0] = 0.f; ls[mf][1] = 0.f; }

  for (int kt = 0; kt < 24; kt++){           // 16 keys per step
    const int kbase = kt*16;
    // K B-fragments (LDS.64 each)
    uint2 kh[2];
    #pragma unroll
    for (int nf = 0; nf < 2; nf++)
      kh[nf] = *(const uint2*)(sK + (kbase + nf*8 + grp)*32 + tig*8);
    // V B-fragments (LDS.64 each)
    uint2 vv[2];
    #pragma unroll
    for (int cn = 0; cn < 2; cn++)
      vv[cn] = *(const uint2*)(sVt + (cn*8 + grp)*VSTRIDE + kt*32 + tig*8);
    // S = Q*K^T, single fp16 MMA
    float s[3][2][4];
    #pragma unroll
    for (int mf = 0; mf < 3; mf++)
      #pragma unroll
      for (int nf = 0; nf < 2; nf++){
        #pragma unroll
        for (int r = 0; r < 4; r++) s[mf][nf][r] = 0.f;
        mma_f16(s[mf][nf], aq[mf], kh[nf].x, kh[nf].y);
      }
    // softmax exp (fp32 stats; scores bounded, no max pass)
    #pragma unroll
    for (int mf = 0; mf < 3; mf++){
      float la = 0.f, lb = 0.f;
      #pragma unroll
      for (int nf = 0; nf < 2; nf++){
        s[mf][nf][0] = ex2f(s[mf][nf][0]);
        s[mf][nf][1] = ex2f(s[mf][nf][1]);
        s[mf][nf][2] = ex2f(s[mf][nf][2]);
        s[mf][nf][3] = ex2f(s[mf][nf][3]);
        la += s[mf][nf][0] + s[mf][nf][1];
        lb += s[mf][nf][2] + s[mf][nf][3];
      }
      ls[mf][0] += la; ls[mf][1] += lb;
    }
    // O += P*V, single fp16 MMA (P packed to fp16 A-frags, zero movement)
    #pragma unroll
    for (int mf = 0; mf < 3; mf++){
      u32 ph[4];
      ph[0] = cvt_h2(s[mf][0][0], s[mf][0][1]);
      ph[1] = cvt_h2(s[mf][0][2], s[mf][0][3]);
      ph[2] = cvt_h2(s[mf][1][0], s[mf][1][1]);
      ph[3] = cvt_h2(s[mf][1][2], s[mf][1][3]);
      #pragma unroll
      for (int cn = 0; cn < 2; cn++)
        mma_f16(o[mf][cn], ph, vv[cn].x, vv[cn].y);
    }
  }

  // reduce lsum across the 4 threads of each row group
  #pragma unroll
  for (int mf = 0; mf < 3; mf++){
    #pragma unroll
    for (int rs = 0; rs < 2; rs++){
      float r = ls[mf][rs];
      r += __shfl_xor_sync(0xffffffffu, r, 1);
      r += __shfl_xor_sync(0xffffffffu, r, 2);
      ls[mf][rs] = 1.0f / r;
    }
  }

  // ---- epilogue: conv + bias + normalize + store ----
  #pragma unroll
  for (int mf = 0; mf < 3; mf++){
    #pragma unroll
    for (int rs = 0; rs < 2; rs++){
      int m = wid*48 + mf*16 + grp + rs*8;
      int hl = m >> 3, w = m & 7;
      float rinv = ls[mf][rs];
      float* orow = out + bbase + (size_t)(hl*WWD + wb0 + w)*CC + c0;
      #pragma unroll
      for (int cn = 0; cn < 2; cn++){
        int cp = cn*4 + tig;     // channel pair index
        ull acc = sB2[cp];
        #pragma unroll
        for (int t = 0; t < 9; t++){
          int dy = t/3, dx = t - dy*3;
          ull vp = *(const ull*)(halo + ((hl+dy)*10 + (w+dx))*16 + cp*2);
          acc = ffma2(sW2[t*8+cp], vp, acc);
        }
        float2 cv = unpack2(acc);
        float2 res;
        res.x = o[mf][cn][rs*2]   * rinv + cv.x;
        res.y = o[mf][cn][rs*2+1] * rinv + cv.y;
        *(float2*)(orow + cn*8 + 2*tig) = res;
      }
    }
  }
}

// ---------------------------------------------------------------------------
extern "C" void kernel_launch(void* const* d_in, const int* in_sizes, int n_in,
                              void* d_out, int out_size){
  const float* q    = (const float*)d_in[0];
  const float* k    = (const float*)d_in[1];
  const float* v    = (const float*)d_in[2];
  const float* p1w  = (const float*)d_in[3];
  const float* p1b  = (const float*)d_in[4];
  const float* bng  = (const float*)d_in[5];
  const float* bnb  = (const float*)d_in[6];
  const float* bnm  = (const float*)d_in[7];
  const float* bnv  = (const float*)d_in[8];
  const float* p2w  = (const float*)d_in[9];
  const float* p2b  = (const float*)d_in[10];
  const float* dynw = (const float*)d_in[11];
  const float* dynb = (const float*)d_in[12];
  float* out = (float*)d_out;

  cudaFuncSetAttribute(proj_kernel, cudaFuncAttributeMaxDynamicSharedMemorySize, 90112);
  cudaFuncSetAttribute(attn_kernel, cudaFuncAttributeMaxDynamicSharedMemorySize, SMEM_SZ);

  pool_kernel<<<dim3(9, BB, 4), 512>>>(v);
  proj_kernel<<<BB, 256, 88320>>>(p1w, p1b, bng, bnb, bnm, bnv, p2w, p2b, dynw, dynb);
  attn_kernel<<<dim3(NHH, NWIN, BB), 256, SMEM_SZ>>>(q, k, v, out);
}

// round 7
// speedup vs baseline: 5.0478x; 1.1367x over previous
#include <cuda_runtime.h>
#include <cuda_bf16.h>
#include <cuda_fp16.h>
#include <cstdint>

#define BB 16
#define HH 48
#define WWD 48
#define CC 128
#define NHH 8
#define SSW 8
#define LL (HH*WWD)
#define HD (CC/NHH)          // 16
#define NWIN (WWD/SSW)       // 6
#define SEQ (HH*SSW)         // 384

// scratch (no allocations allowed)
__device__ float g_pooled[BB*9*CC];
__device__ float g_w[BB*CC*9];
__device__ float g_bias[BB*CC];

typedef unsigned long long ull;
typedef unsigned int u32;

__device__ __forceinline__ ull ffma2(ull a, ull b, ull c){
  ull d; asm("fma.rn.f32x2 %0,%1,%2,%3;" : "=l"(d) : "l"(a), "l"(b), "l"(c)); return d;
}
__device__ __forceinline__ float2 unpack2(ull a){
  float2 r; asm("mov.b64 {%0,%1},%2;" : "=f"(r.x), "=f"(r.y) : "l"(a)); return r;
}
__device__ __forceinline__ float ex2f(float x){
  float r; asm("ex2.approx.ftz.f32 %0,%1;" : "=f"(r) : "f"(x)); return r;
}
// pack {lo=f16(x), hi=f16(y)}
__device__ __forceinline__ u32 cvt_h2(float x, float y){
  u32 d; asm("cvt.rn.f16x2.f32 %0,%1,%2;" : "=r"(d) : "f"(y), "f"(x)); return d;
}
__device__ __forceinline__ void mma_f16(float (&d)[4], const u32 (&a)[4], u32 b0, u32 b1){
  asm volatile("mma.sync.aligned.m16n8k16.row.col.f32.f16.f16.f32 "
    "{%0,%1,%2,%3}, {%4,%5,%6,%7}, {%8,%9}, {%0,%1,%2,%3};"
    : "+f"(d[0]), "+f"(d[1]), "+f"(d[2]), "+f"(d[3])
    : "r"(a[0]), "r"(a[1]), "r"(a[2]), "r"(a[3]), "r"(b0), "r"(b1));
}

// ---------------------------------------------------------------------------
// Kernel 1: adaptive avg pool to 3x3 (uniform 16x16 block means)
// ---------------------------------------------------------------------------
__global__ void pool_kernel(const float* __restrict__ v){
  const int bin = blockIdx.x, b = blockIdx.y, ch = blockIdx.z;
  const int ky = bin / 3, kx = bin - ky*3;
  const int tid = threadIdx.x;
  const int c4 = tid & 7, part = tid >> 3;
  const int row = part >> 2, quad = part & 3;
  const int cg = ch*8 + c4;
  const float4* vb = (const float4*)(v + (size_t)b*LL*CC);
  const int h = ky*16 + row;
  const float4* p = vb + (size_t)(h*WWD + kx*16 + quad*4)*(CC/4) + cg;
  float4 s = make_float4(0.f,0.f,0.f,0.f);
  #pragma unroll
  for (int ww = 0; ww < 4; ww++){
    float4 t = p[ww*(CC/4)];
    s.x += t.x; s.y += t.y; s.z += t.z; s.w += t.w;
  }
  __shared__ float4 red[512];
  red[tid] = s; __syncthreads();
  #pragma unroll
  for (int off = 256; off >= 8; off >>= 1){
    if (tid < off){
      float4 o = red[tid+off];
      s.x += o.x; s.y += o.y; s.z += o.z; s.w += o.w;
      red[tid] = s;
    }
    __syncthreads();
  }
  if (tid < 8){
    s.x *= (1.f/256.f); s.y *= (1.f/256.f); s.z *= (1.f/256.f); s.w *= (1.f/256.f);
    ((float4*)g_pooled)[(b*9 + bin)*32 + ch*8 + tid] = s;
  }
}

// ---------------------------------------------------------------------------
// Kernel 2: proj MLP, one (batch, position) per block; pos 9 = global mean
// grid (16, 10), 128 threads
// ---------------------------------------------------------------------------
__global__ void proj_kernel(const float* __restrict__ p1w, const float* __restrict__ p1b,
                            const float* __restrict__ bng, const float* __restrict__ bnb,
                            const float* __restrict__ bnm, const float* __restrict__ bnv,
                            const float* __restrict__ p2w, const float* __restrict__ p2b,
                            const float* __restrict__ dynw, const float* __restrict__ dynb){
  const int b = blockIdx.x, pos = blockIdx.y;
  const int tid = threadIdx.x;
  __shared__ float prow[128];
  __shared__ float act[32];

  {
    float s;
    if (pos < 9) s = g_pooled[(b*9 + pos)*CC + tid];
    else {
      s = 0.f;
      #pragma unroll
      for (int qq = 0; qq < 9; qq++) s += g_pooled[(b*9 + qq)*CC + tid];
      s *= (1.f/9.f);
    }
    prow[tid] = s;
  }
  __syncthreads();

  if (tid < 32){
    const int o = tid;
    float s = p1b[o];
    const float4* w = (const float4*)(p1w + o*CC);
    #pragma unroll 8
    for (int i = 0; i < 32; i++){
      float4 ww = w[i];
      s += ww.x*prow[4*i] + ww.y*prow[4*i+1] + ww.z*prow[4*i+2] + ww.w*prow[4*i+3];
    }
    float inv = rsqrtf(bnv[o] + 1e-5f);
    s = (s - bnm[o]) * (inv * bng[o]) + bnb[o];
    s = 0.5f * s * (1.f + erff(s * 0.70710678118654752f));
    act[o] = s;
  }
  __syncthreads();

  {
    const int c = tid;
    float y[4];
    #pragma unroll
    for (int g = 0; g < 4; g++){
      int oc = g*CC + c;
      float s = p2b[oc];
      const float4* w = (const float4*)(p2w + oc*32);
      #pragma unroll
      for (int i = 0; i < 8; i++){
        float4 ww = w[i];
        s += ww.x*act[4*i] + ww.y*act[4*i+1] + ww.z*act[4*i+2] + ww.w*act[4*i+3];
      }
      y[g] = s;
    }
    float m = fmaxf(fmaxf(y[0],y[1]), fmaxf(y[2],y[3]));
    float e0 = expf(y[0]-m), e1 = expf(y[1]-m), e2 = expf(y[2]-m), e3 = expf(y[3]-m);
    float rs = 1.f / (e0+e1+e2+e3);
    if (pos < 9){
      float wv = e0*dynw[(0*CC+c)*9+pos] + e1*dynw[(1*CC+c)*9+pos]
               + e2*dynw[(2*CC+c)*9+pos] + e3*dynw[(3*CC+c)*9+pos];
      g_w[(b*CC + c)*9 + pos] = wv * rs;
    } else {
      float bv = e0*dynb[0*CC+c] + e1*dynb[1*CC+c] + e2*dynb[2*CC+c] + e3*dynb[3*CC+c];
      g_bias[b*CC + c] = bv * rs;
    }
  }
}

// ---------------------------------------------------------------------------
// Kernel 3: tensor-core attention, fp16 single-MMA, software-pipelined so
// next step's QK MMAs overlap current step's ex2/pack/PV (breaks the
// MUFU/tensor burst phase-lock).
// grid (8 heads, 6 wblks, 16 batches), 256 threads = 8 warps x 48 queries
// ---------------------------------------------------------------------------
#define KOFF    0
#define VOFF    12288
#define VSTRIDE 800
#define HOFF    25088
#define W2_OFF  57088
#define B2_OFF  57664
#define SMEM_SZ 57728

__global__ void __launch_bounds__(256, 2)
attn_kernel(const float* __restrict__ q, const float* __restrict__ k,
            const float* __restrict__ v, float* __restrict__ out){
  extern __shared__ char smem[];
  char* sK  = smem + KOFF;
  char* sVt = smem + VOFF;
  float* halo = (float*)(smem + HOFF);   // [50][10][16] f32
  ull* sW2 = (ull*)(smem + W2_OFF);      // [9][8]
  ull* sB2 = (ull*)(smem + B2_OFF);      // [8]

  const int head = blockIdx.x, wblk = blockIdx.y, b = blockIdx.z;
  const int c0 = head*HD;
  const int wb0 = wblk*SSW;
  const int tid = threadIdx.x;
  const int wid = tid >> 5, lane = tid & 31;
  const int grp = lane >> 2, tig = lane & 3;
  const size_t bbase = (size_t)b*LL*CC;

  // ---- fill K (fp16, slot-permuted) ----
  for (int i = tid; i < SEQ*4; i += 256){
    int key = i >> 2, dq = (i & 3)*4;
    int hj = key >> 3, wj = key & 7;
    float4 kv = *(const float4*)(k + bbase + (size_t)(hj*WWD + wb0 + wj)*CC + c0 + dq);
    int j0 = dq >> 1;                         // pair index 0,2,4,6
    int s0 = (j0 < 4) ? 2*j0 : 2*j0 - 7;
    int s1 = (j0+1 < 4) ? 2*(j0+1) : 2*(j0+1) - 7;
    u32* row = (u32*)(sK + key*32);
    row[s0] = cvt_h2(kv.x, kv.y);
    row[s1] = cvt_h2(kv.z, kv.w);
  }
  // ---- fill Vt (fp16 transposed, slot-permuted per 16-key block) ----
  for (int i = tid; i < SEQ*4; i += 256){
    int key = i >> 2, dq = (i & 3)*4;
    int hj = key >> 3, wj = key & 7;
    float4 vv = *(const float4*)(v + bbase + (size_t)(hj*WWD + wb0 + wj)*CC + c0 + dq);
    float vals[4] = {vv.x, vv.y, vv.z, vv.w};
    int blk = key >> 4, r = key & 15;
    int pr = r >> 1;
    int slot = (r < 8) ? 2*pr : 2*(pr-4)+1;
    int byte = blk*32 + slot*4 + (r & 1)*2;
    #pragma unroll
    for (int d = 0; d < 4; d++)
      *(__half*)(sVt + (dq+d)*VSTRIDE + byte) = __float2half(vals[d]);
  }
  // ---- fill fp32 halo for conv ----
  for (int i = tid; i < 50*10*4; i += 256){
    int pos = i >> 2, dq = i & 3;
    int hh = pos / 10, ww = pos - hh*10;
    int gh = hh - 1, gw = wb0 + ww - 1;
    float4 val = make_float4(0.f,0.f,0.f,0.f);
    if (gh >= 0 && gh < HH && gw >= 0 && gw < WWD)
      val = *(const float4*)(v + bbase + (size_t)(gh*WWD + gw)*CC + c0 + dq*4);
    ((float4*)halo)[pos*4 + dq] = val;
  }
  if (tid < 72){
    int t = tid >> 3, i = tid & 7;
    float2 wp = make_float2(g_w[(b*CC + c0 + 2*i)*9 + t], g_w[(b*CC + c0 + 2*i+1)*9 + t]);
    sW2[t*8+i] = *(ull*)&wp;
  }
  if (tid < 8){
    float2 bp = make_float2(g_bias[b*CC + c0 + 2*tid], g_bias[b*CC + c0 + 2*tid+1]);
    sB2[tid] = *(ull*)&bp;
  }

  // ---- Q fragments (scaled fp16) ----
  const float SCL = 0.36067376022224085f;  // 0.25 * log2(e)
  u32 aq[3][4];
  #pragma unroll
  for (int mf = 0; mf < 3; mf++){
    #pragma unroll
    for (int rs = 0; rs < 2; rs++){
      int m = wid*48 + mf*16 + grp + rs*8;     // query 0..383
      int hl = m >> 3, w = m & 7;
      const float* qr = q + bbase + (size_t)(hl*WWD + wb0 + w)*CC + c0;
      float2 qa = *(const float2*)(qr + 2*tig);
      float2 qb = *(const float2*)(qr + 2*tig + 8);
      aq[mf][rs]   = cvt_h2(qa.x*SCL, qa.y*SCL);
      aq[mf][rs+2] = cvt_h2(qb.x*SCL, qb.y*SCL);
    }
  }
  __syncthreads();

  float o[3][2][4];
  #pragma unroll
  for (int mf = 0; mf < 3; mf++)
    #pragma unroll
    for (int cn = 0; cn < 2; cn++)
      #pragma unroll
      for (int r = 0; r < 4; r++) o[mf][cn][r] = 0.f;
  float ls[3][2];
  #pragma unroll
  for (int mf = 0; mf < 3; mf++){ ls[mf][0] = 0.f; ls[mf][1] = 0.f; }

  // ---- software-pipelined mainloop: QK(t+1) overlaps ex2/PV(t) ----
  float sA[3][2][4], sB[3][2][4];

  // prologue: QK for step 0 into sA
  {
    uint2 kh[2];
    #pragma unroll
    for (int nf = 0; nf < 2; nf++)
      kh[nf] = *(const uint2*)(sK + (nf*8 + grp)*32 + tig*8);
    #pragma unroll
    for (int mf = 0; mf < 3; mf++)
      #pragma unroll
      for (int nf = 0; nf < 2; nf++){
        #pragma unroll
        for (int r = 0; r < 4; r++) sA[mf][nf][r] = 0.f;
        mma_f16(sA[mf][nf], aq[mf], kh[nf].x, kh[nf].y);
      }
  }

  #define STEP_BODY(T, SCUR, SNEXT)                                          \
  {                                                                          \
    const int t_ = (T);                                                      \
    const int tn_ = (t_ + 1 < 24) ? t_ + 1 : 0;                              \
    uint2 khn[2];                                                            \
    _Pragma("unroll")                                                        \
    for (int nf = 0; nf < 2; nf++)                                           \
      khn[nf] = *(const uint2*)(sK + (tn_*16 + nf*8 + grp)*32 + tig*8);      \
    uint2 vv[2];                                                             \
    _Pragma("unroll")                                                        \
    for (int cn = 0; cn < 2; cn++)                                           \
      vv[cn] = *(const uint2*)(sVt + (cn*8 + grp)*VSTRIDE + t_*32 + tig*8);  \
    if (t_ + 1 < 24){                                                        \
      _Pragma("unroll")                                                      \
      for (int mf = 0; mf < 3; mf++)                                         \
        _Pragma("unroll")                                                    \
        for (int nf = 0; nf < 2; nf++){                                      \
          _Pragma("unroll")                                                  \
          for (int r = 0; r < 4; r++) SNEXT[mf][nf][r] = 0.f;                \
          mma_f16(SNEXT[mf][nf], aq[mf], khn[nf].x, khn[nf].y);              \
        }                                                                    \
    }                                                                        \
    _Pragma("unroll")                                                        \
    for (int mf = 0; mf < 3; mf++){                                          \
      _Pragma("unroll")                                                      \
      for (int nf = 0; nf < 2; nf++){                                        \
        SCUR[mf][nf][0] = ex2f(SCUR[mf][nf][0]);                             \
        SCUR[mf][nf][1] = ex2f(SCUR[mf][nf][1]);                             \
        SCUR[mf][nf][2] = ex2f(SCUR[mf][nf][2]);                             \
        SCUR[mf][nf][3] = ex2f(SCUR[mf][nf][3]);                             \
      }                                                                      \
      ls[mf][0] += (SCUR[mf][0][0] + SCUR[mf][0][1])                         \
                 + (SCUR[mf][1][0] + SCUR[mf][1][1]);                        \
      ls[mf][1] += (SCUR[mf][0][2] + SCUR[mf][0][3])                         \
                 + (SCUR[mf][1][2] + SCUR[mf][1][3]);                        \
      u32 ph[4];                                                             \
      ph[0] = cvt_h2(SCUR[mf][0][0], SCUR[mf][0][1]);                        \
      ph[1] = cvt_h2(SCUR[mf][0][2], SCUR[mf][0][3]);                        \
      ph[2] = cvt_h2(SCUR[mf][1][0], SCUR[mf][1][1]);                        \
      ph[3] = cvt_h2(SCUR[mf][1][2], SCUR[mf][1][3]);                        \
      mma_f16(o[mf][0], ph, vv[0].x, vv[0].y);                               \
      mma_f16(o[mf][1], ph, vv[1].x, vv[1].y);                               \
    }                                                                        \
  }

  for (int kt = 0; kt < 24; kt += 2){
    STEP_BODY(kt,   sA, sB)
    STEP_BODY(kt+1, sB, sA)
  }
  #undef STEP_BODY

  // reduce lsum across the 4 threads of each row group
  #pragma unroll
  for (int mf = 0; mf < 3; mf++){
    #pragma unroll
    for (int rs = 0; rs < 2; rs++){
      float r = ls[mf][rs];
      r += __shfl_xor_sync(0xffffffffu, r, 1);
      r += __shfl_xor_sync(0xffffffffu, r, 2);
      ls[mf][rs] = 1.0f / r;
    }
  }

  // ---- epilogue: conv + bias + normalize + store ----
  #pragma unroll
  for (int mf = 0; mf < 3; mf++){
    #pragma unroll
    for (int rs = 0; rs < 2; rs++){
      int m = wid*48 + mf*16 + grp + rs*8;
      int hl = m >> 3, w = m & 7;
      float rinv = ls[mf][rs];
      float* orow = out + bbase + (size_t)(hl*WWD + wb0 + w)*CC + c0;
      #pragma unroll
      for (int cn = 0; cn < 2; cn++){
        int cp = cn*4 + tig;     // channel pair index
        ull acc = sB2[cp];
        #pragma unroll
        for (int t = 0; t < 9; t++){
          int dy = t/3, dx = t - dy*3;
          ull vp = *(const ull*)(halo + ((hl+dy)*10 + (w+dx))*16 + cp*2);
          acc = ffma2(sW2[t*8+cp], vp, acc);
        }
        float2 cv = unpack2(acc);
        float2 res;
        res.x = o[mf][cn][rs*2]   * rinv + cv.x;
        res.y = o[mf][cn][rs*2+1] * rinv + cv.y;
        *(float2*)(orow + cn*8 + 2*tig) = res;
      }
    }
  }
}

// ---------------------------------------------------------------------------
extern "C" void kernel_launch(void* const* d_in, const int* in_sizes, int n_in,
                              void* d_out, int out_size){
  const float* q    = (const float*)d_in[0];
  const float* k    = (const float*)d_in[1];
  const float* v    = (const float*)d_in[2];
  const float* p1w  = (const float*)d_in[3];
  const float* p1b  = (const float*)d_in[4];
  const float* bng  = (const float*)d_in[5];
  const float* bnb  = (const float*)d_in[6];
  const float* bnm  = (const float*)d_in[7];
  const float* bnv  = (const float*)d_in[8];
  const float* p2w  = (const float*)d_in[9];
  const float* p2b  = (const float*)d_in[10];
  const float* dynw = (const float*)d_in[11];
  const float* dynb = (const float*)d_in[12];
  float* out = (float*)d_out;

  cudaFuncSetAttribute(attn_kernel, cudaFuncAttributeMaxDynamicSharedMemorySize, SMEM_SZ);

  pool_kernel<<<dim3(9, BB, 4), 512>>>(v);
  proj_kernel<<<dim3(BB, 10), 128>>>(p1w, p1b, bng, bnb, bnm, bnv, p2w, p2b, dynw, dynb);
  attn_kernel<<<dim3(NHH, NWIN, BB), 256, SMEM_SZ>>>(q, k, v, out);
}

// round 8
// speedup vs baseline: 5.0531x; 1.0010x over previous
#include <cuda_runtime.h>
#include <cuda_bf16.h>
#include <cuda_fp16.h>
#include <cstdint>

#define BB 16
#define HH 48
#define WWD 48
#define CC 128
#define NHH 8
#define SSW 8
#define LL (HH*WWD)
#define HD (CC/NHH)          // 16
#define NWIN (WWD/SSW)       // 6
#define SEQ (HH*SSW)         // 384

// scratch (no allocations allowed)
__device__ float g_pooled[BB*9*CC];
__device__ float g_w[BB*CC*9];
__device__ float g_bias[BB*CC];

typedef unsigned long long ull;
typedef unsigned int u32;

__device__ __forceinline__ ull ffma2(ull a, ull b, ull c){
  ull d; asm("fma.rn.f32x2 %0,%1,%2,%3;" : "=l"(d) : "l"(a), "l"(b), "l"(c)); return d;
}
__device__ __forceinline__ float2 unpack2(ull a){
  float2 r; asm("mov.b64 {%0,%1},%2;" : "=f"(r.x), "=f"(r.y) : "l"(a)); return r;
}
__device__ __forceinline__ float ex2f(float x){
  float r; asm("ex2.approx.ftz.f32 %0,%1;" : "=f"(r) : "f"(x)); return r;
}
// pack {lo=f16(x), hi=f16(y)}
__device__ __forceinline__ u32 cvt_h2(float x, float y){
  u32 d; asm("cvt.rn.f16x2.f32 %0,%1,%2;" : "=r"(d) : "f"(y), "f"(x)); return d;
}
__device__ __forceinline__ void mma_f16(float (&d)[4], const u32 (&a)[4], u32 b0, u32 b1){
  asm volatile("mma.sync.aligned.m16n8k16.row.col.f32.f16.f16.f32 "
    "{%0,%1,%2,%3}, {%4,%5,%6,%7}, {%8,%9}, {%0,%1,%2,%3};"
    : "+f"(d[0]), "+f"(d[1]), "+f"(d[2]), "+f"(d[3])
    : "r"(a[0]), "r"(a[1]), "r"(a[2]), "r"(a[3]), "r"(b0), "r"(b1));
}

// ---------------------------------------------------------------------------
// Kernel 1: adaptive avg pool to 3x3 (uniform 16x16 block means)
// grid (9, 16, 2), 512 threads, 8 float4 loads each (MLP 8)
// ---------------------------------------------------------------------------
__global__ void pool_kernel(const float* __restrict__ v){
  const int bin = blockIdx.x, b = blockIdx.y, ch = blockIdx.z;
  const int ky = bin / 3, kx = bin - ky*3;
  const int tid = threadIdx.x;
  const int c4 = tid & 15, part = tid >> 4;    // 16 ch-groups, 32 parts
  const int row = part >> 1, wh = part & 1;    // 16 rows x 2 col-halves
  const int cg = ch*16 + c4;
  const float4* vb = (const float4*)(v + (size_t)b*LL*CC);
  const int h = ky*16 + row;
  const float4* p = vb + (size_t)(h*WWD + kx*16 + wh*8)*(CC/4) + cg;
  float4 s = make_float4(0.f,0.f,0.f,0.f);
  #pragma unroll
  for (int ww = 0; ww < 8; ww++){
    float4 t = p[ww*(CC/4)];
    s.x += t.x; s.y += t.y; s.z += t.z; s.w += t.w;
  }
  __shared__ float4 red[512];
  red[tid] = s; __syncthreads();
  #pragma unroll
  for (int off = 256; off >= 16; off >>= 1){
    if (tid < off){
      float4 o = red[tid+off];
      s.x += o.x; s.y += o.y; s.z += o.z; s.w += o.w;
      red[tid] = s;
    }
    __syncthreads();
  }
  if (tid < 16){
    s.x *= (1.f/256.f); s.y *= (1.f/256.f); s.z *= (1.f/256.f); s.w *= (1.f/256.f);
    ((float4*)g_pooled)[(b*9 + bin)*32 + ch*16 + tid] = s;
  }
}

// ---------------------------------------------------------------------------
// Kernel 2: proj MLP, one (batch, position) per block; pos 9 = global mean
// ---------------------------------------------------------------------------
__global__ void proj_kernel(const float* __restrict__ p1w, const float* __restrict__ p1b,
                            const float* __restrict__ bng, const float* __restrict__ bnb,
                            const float* __restrict__ bnm, const float* __restrict__ bnv,
                            const float* __restrict__ p2w, const float* __restrict__ p2b,
                            const float* __restrict__ dynw, const float* __restrict__ dynb){
  const int b = blockIdx.x, pos = blockIdx.y;
  const int tid = threadIdx.x;
  __shared__ float prow[128];
  __shared__ float act[32];

  {
    float s;
    if (pos < 9) s = g_pooled[(b*9 + pos)*CC + tid];
    else {
      s = 0.f;
      #pragma unroll
      for (int qq = 0; qq < 9; qq++) s += g_pooled[(b*9 + qq)*CC + tid];
      s *= (1.f/9.f);
    }
    prow[tid] = s;
  }
  __syncthreads();

  if (tid < 32){
    const int o = tid;
    float s = p1b[o];
    const float4* w = (const float4*)(p1w + o*CC);
    #pragma unroll 8
    for (int i = 0; i < 32; i++){
      float4 ww = w[i];
      s += ww.x*prow[4*i] + ww.y*prow[4*i+1] + ww.z*prow[4*i+2] + ww.w*prow[4*i+3];
    }
    float inv = rsqrtf(bnv[o] + 1e-5f);
    s = (s - bnm[o]) * (inv * bng[o]) + bnb[o];
    s = 0.5f * s * (1.f + erff(s * 0.70710678118654752f));
    act[o] = s;
  }
  __syncthreads();

  {
    const int c = tid;
    float y[4];
    #pragma unroll
    for (int g = 0; g < 4; g++){
      int oc = g*CC + c;
      float s = p2b[oc];
      const float4* w = (const float4*)(p2w + oc*32);
      #pragma unroll
      for (int i = 0; i < 8; i++){
        float4 ww = w[i];
        s += ww.x*act[4*i] + ww.y*act[4*i+1] + ww.z*act[4*i+2] + ww.w*act[4*i+3];
      }
      y[g] = s;
    }
    float m = fmaxf(fmaxf(y[0],y[1]), fmaxf(y[2],y[3]));
    float e0 = expf(y[0]-m), e1 = expf(y[1]-m), e2 = expf(y[2]-m), e3 = expf(y[3]-m);
    float rs = 1.f / (e0+e1+e2+e3);
    if (pos < 9){
      float wv = e0*dynw[(0*CC+c)*9+pos] + e1*dynw[(1*CC+c)*9+pos]
               + e2*dynw[(2*CC+c)*9+pos] + e3*dynw[(3*CC+c)*9+pos];
      g_w[(b*CC + c)*9 + pos] = wv * rs;
    } else {
      float bv = e0*dynb[0*CC+c] + e1*dynb[1*CC+c] + e2*dynb[2*CC+c] + e3*dynb[3*CC+c];
      g_bias[b*CC + c] = bv * rs;
    }
  }
}

// ---------------------------------------------------------------------------
// Kernel 3: tensor-core attention, fp16 single-MMA, software-pipelined AND
// warp-skewed: warp w starts the 24-step key ring at step w*3, so warps on an
// SMSP are never in the same MUFU/HMMA phase (breaks cross-warp phase-lock).
// QK(t+1) MMAs interleaved per-mf into the ex2/PV blocks.
// grid (8 heads, 6 wblks, 16 batches), 256 threads = 8 warps x 48 queries
// ---------------------------------------------------------------------------
#define KOFF    0
#define VOFF    12288
#define VSTRIDE 800
#define HOFF    25088
#define W2_OFF  57088
#define B2_OFF  57664
#define SMEM_SZ 57728

__global__ void __launch_bounds__(256, 2)
attn_kernel(const float* __restrict__ q, const float* __restrict__ k,
            const float* __restrict__ v, float* __restrict__ out){
  extern __shared__ char smem[];
  char* sK  = smem + KOFF;
  char* sVt = smem + VOFF;
  float* halo = (float*)(smem + HOFF);   // [50][10][16] f32
  ull* sW2 = (ull*)(smem + W2_OFF);      // [9][8]
  ull* sB2 = (ull*)(smem + B2_OFF);      // [8]

  const int head = blockIdx.x, wblk = blockIdx.y, b = blockIdx.z;
  const int c0 = head*HD;
  const int wb0 = wblk*SSW;
  const int tid = threadIdx.x;
  const int wid = tid >> 5, lane = tid & 31;
  const int grp = lane >> 2, tig = lane & 3;
  const size_t bbase = (size_t)b*LL*CC;

  // ---- fill K (fp16, slot-permuted) ----
  for (int i = tid; i < SEQ*4; i += 256){
    int key = i >> 2, dq = (i & 3)*4;
    int hj = key >> 3, wj = key & 7;
    float4 kv = *(const float4*)(k + bbase + (size_t)(hj*WWD + wb0 + wj)*CC + c0 + dq);
    int j0 = dq >> 1;                         // pair index 0,2,4,6
    int s0 = (j0 < 4) ? 2*j0 : 2*j0 - 7;
    int s1 = (j0+1 < 4) ? 2*(j0+1) : 2*(j0+1) - 7;
    u32* row = (u32*)(sK + key*32);
    row[s0] = cvt_h2(kv.x, kv.y);
    row[s1] = cvt_h2(kv.z, kv.w);
  }
  // ---- fill Vt (fp16 transposed, slot-permuted per 16-key block) ----
  for (int i = tid; i < SEQ*4; i += 256){
    int key = i >> 2, dq = (i & 3)*4;
    int hj = key >> 3, wj = key & 7;
    float4 vv = *(const float4*)(v + bbase + (size_t)(hj*WWD + wb0 + wj)*CC + c0 + dq);
    float vals[4] = {vv.x, vv.y, vv.z, vv.w};
    int blk = key >> 4, r = key & 15;
    int pr = r >> 1;
    int slot = (r < 8) ? 2*pr : 2*(pr-4)+1;
    int byte = blk*32 + slot*4 + (r & 1)*2;
    #pragma unroll
    for (int d = 0; d < 4; d++)
      *(__half*)(sVt + (dq+d)*VSTRIDE + byte) = __float2half(vals[d]);
  }
  // ---- fill fp32 halo for conv ----
  for (int i = tid; i < 50*10*4; i += 256){
    int pos = i >> 2, dq = i & 3;
    int hh = pos / 10, ww = pos - hh*10;
    int gh = hh - 1, gw = wb0 + ww - 1;
    float4 val = make_float4(0.f,0.f,0.f,0.f);
    if (gh >= 0 && gh < HH && gw >= 0 && gw < WWD)
      val = *(const float4*)(v + bbase + (size_t)(gh*WWD + gw)*CC + c0 + dq*4);
    ((float4*)halo)[pos*4 + dq] = val;
  }
  if (tid < 72){
    int t = tid >> 3, i = tid & 7;
    float2 wp = make_float2(g_w[(b*CC + c0 + 2*i)*9 + t], g_w[(b*CC + c0 + 2*i+1)*9 + t]);
    sW2[t*8+i] = *(ull*)&wp;
  }
  if (tid < 8){
    float2 bp = make_float2(g_bias[b*CC + c0 + 2*tid], g_bias[b*CC + c0 + 2*tid+1]);
    sB2[tid] = *(ull*)&bp;
  }

  // ---- Q fragments (scaled fp16) ----
  const float SCL = 0.36067376022224085f;  // 0.25 * log2(e)
  u32 aq[3][4];
  #pragma unroll
  for (int mf = 0; mf < 3; mf++){
    #pragma unroll
    for (int rs = 0; rs < 2; rs++){
      int m = wid*48 + mf*16 + grp + rs*8;     // query 0..383
      int hl = m >> 3, w = m & 7;
      const float* qr = q + bbase + (size_t)(hl*WWD + wb0 + w)*CC + c0;
      float2 qa = *(const float2*)(qr + 2*tig);
      float2 qb = *(const float2*)(qr + 2*tig + 8);
      aq[mf][rs]   = cvt_h2(qa.x*SCL, qa.y*SCL);
      aq[mf][rs+2] = cvt_h2(qb.x*SCL, qb.y*SCL);
    }
  }
  __syncthreads();

  float o[3][2][4];
  #pragma unroll
  for (int mf = 0; mf < 3; mf++)
    #pragma unroll
    for (int cn = 0; cn < 2; cn++)
      #pragma unroll
      for (int r = 0; r < 4; r++) o[mf][cn][r] = 0.f;
  float ls[3][2];
  #pragma unroll
  for (int mf = 0; mf < 3; mf++){ ls[mf][0] = 0.f; ls[mf][1] = 0.f; }

  // ---- warp-skewed, software-pipelined mainloop over the 24-step key ring ----
  float sA[3][2][4], sB[3][2][4];
  const int start = wid*3;                 // per-warp phase offset
  int tcur = start;

  // prologue: QK for this warp's first step into sA
  {
    uint2 kh[2];
    #pragma unroll
    for (int nf = 0; nf < 2; nf++)
      kh[nf] = *(const uint2*)(sK + (tcur*16 + nf*8 + grp)*32 + tig*8);
    #pragma unroll
    for (int mf = 0; mf < 3; mf++)
      #pragma unroll
      for (int nf = 0; nf < 2; nf++){
        #pragma unroll
        for (int r = 0; r < 4; r++) sA[mf][nf][r] = 0.f;
        mma_f16(sA[mf][nf], aq[mf], kh[nf].x, kh[nf].y);
      }
  }

  // step body: ex2/pack/PV for SCUR at step t_, QK for SNEXT at step tn_
  // (QK MMAs interleaved 2-per-mf to spread HMMA against MUFU)
  #define STEP_BODY(IT, SCUR, SNEXT)                                          \
  {                                                                           \
    const int t_  = tcur;                                                     \
    const int tn_ = (t_ + 1 < 24) ? t_ + 1 : 0;                               \
    const bool hn_ = (IT) < 23;                                               \
    uint2 khn[2];                                                             \
    if (hn_){                                                                 \
      khn[0] = *(const uint2*)(sK + (tn_*16 + grp)*32 + tig*8);               \
      khn[1] = *(const uint2*)(sK + (tn_*16 + 8 + grp)*32 + tig*8);           \
    }                                                                         \
    uint2 vv0 = *(const uint2*)(sVt + (grp)*VSTRIDE + t_*32 + tig*8);         \
    uint2 vv1 = *(const uint2*)(sVt + (8 + grp)*VSTRIDE + t_*32 + tig*8);     \
    _Pragma("unroll")                                                         \
    for (int mf = 0; mf < 3; mf++){                                           \
      if (hn_){                                                               \
        _Pragma("unroll")                                                     \
        for (int nf = 0; nf < 2; nf++){                                       \
          _Pragma("unroll")                                                   \
          for (int r = 0; r < 4; r++) SNEXT[mf][nf][r] = 0.f;                 \
          mma_f16(SNEXT[mf][nf], aq[mf], khn[nf].x, khn[nf].y);               \
        }                                                                     \
      }                                                                       \
      _Pragma("unroll")                                                       \
      for (int nf = 0; nf < 2; nf++){                                         \
        SCUR[mf][nf][0] = ex2f(SCUR[mf][nf][0]);                              \
        SCUR[mf][nf][1] = ex2f(SCUR[mf][nf][1]);                              \
        SCUR[mf][nf][2] = ex2f(SCUR[mf][nf][2]);                              \
        SCUR[mf][nf][3] = ex2f(SCUR[mf][nf][3]);                              \
      }                                                                       \
      ls[mf][0] += (SCUR[mf][0][0] + SCUR[mf][0][1])                          \
                 + (SCUR[mf][1][0] + SCUR[mf][1][1]);                         \
      ls[mf][1] += (SCUR[mf][0][2] + SCUR[mf][0][3])                          \
                 + (SCUR[mf][1][2] + SCUR[mf][1][3]);                         \
      u32 ph[4];                                                              \
      ph[0] = cvt_h2(SCUR[mf][0][0], SCUR[mf][0][1]);                         \
      ph[1] = cvt_h2(SCUR[mf][0][2], SCUR[mf][0][3]);                         \
      ph[2] = cvt_h2(SCUR[mf][1][0], SCUR[mf][1][1]);                         \
      ph[3] = cvt_h2(SCUR[mf][1][2], SCUR[mf][1][3]);                         \
      mma_f16(o[mf][0], ph, vv0.x, vv0.y);                                    \
      mma_f16(o[mf][1], ph, vv1.x, vv1.y);                                    \
    }                                                                         \
    tcur = tn_;                                                               \
  }

  for (int it = 0; it < 24; it += 2){
    STEP_BODY(it,   sA, sB)
    STEP_BODY(it+1, sB, sA)
  }
  #undef STEP_BODY

  // reduce lsum across the 4 threads of each row group
  #pragma unroll
  for (int mf = 0; mf < 3; mf++){
    #pragma unroll
    for (int rs = 0; rs < 2; rs++){
      float r = ls[mf][rs];
      r += __shfl_xor_sync(0xffffffffu, r, 1);
      r += __shfl_xor_sync(0xffffffffu, r, 2);
      ls[mf][rs] = 1.0f / r;
    }
  }

  // ---- epilogue: conv + bias + normalize + store ----
  #pragma unroll
  for (int mf = 0; mf < 3; mf++){
    #pragma unroll
    for (int rs = 0; rs < 2; rs++){
      int m = wid*48 + mf*16 + grp + rs*8;
      int hl = m >> 3, w = m & 7;
      float rinv = ls[mf][rs];
      float* orow = out + bbase + (size_t)(hl*WWD + wb0 + w)*CC + c0;
      #pragma unroll
      for (int cn = 0; cn < 2; cn++){
        int cp = cn*4 + tig;     // channel pair index
        ull acc = sB2[cp];
        #pragma unroll
        for (int t = 0; t < 9; t++){
          int dy = t/3, dx = t - dy*3;
          ull vp = *(const ull*)(halo + ((hl+dy)*10 + (w+dx))*16 + cp*2);
          acc = ffma2(sW2[t*8+cp], vp, acc);
        }
        float2 cv = unpack2(acc);
        float2 res;
        res.x = o[mf][cn][rs*2]   * rinv + cv.x;
        res.y = o[mf][cn][rs*2+1] * rinv + cv.y;
        *(float2*)(orow + cn*8 + 2*tig) = res;
      }
    }
  }
}

// ---------------------------------------------------------------------------
extern "C" void kernel_launch(void* const* d_in, const int* in_sizes, int n_in,
                              void* d_out, int out_size){
  const float* q    = (const float*)d_in[0];
  const float* k    = (const float*)d_in[1];
  const float* v    = (const float*)d_in[2];
  const float* p1w  = (const float*)d_in[3];
  const float* p1b  = (const float*)d_in[4];
  const float* bng  = (const float*)d_in[5];
  const float* bnb  = (const float*)d_in[6];
  const float* bnm  = (const float*)d_in[7];
  const float* bnv  = (const float*)d_in[8];
  const float* p2w  = (const float*)d_in[9];
  const float* p2b  = (const float*)d_in[10];
  const float* dynw = (const float*)d_in[11];
  const float* dynb = (const float*)d_in[12];
  float* out = (float*)d_out;

  cudaFuncSetAttribute(attn_kernel, cudaFuncAttributeMaxDynamicSharedMemorySize, SMEM_SZ);

  pool_kernel<<<dim3(9, BB, 2), 512>>>(v);
  proj_kernel<<<dim3(BB, 10), 128>>>(p1w, p1b, bng, bnb, bnm, bnv, p2w, p2b, dynw, dynb);
  attn_kernel<<<dim3(NHH, NWIN, BB), 256, SMEM_SZ>>>(q, k, v, out);
}

// round 9
// speedup vs baseline: 5.7844x; 1.1447x over previous
#include <cuda_runtime.h>
#include <cuda_bf16.h>
#include <cuda_fp16.h>
#include <cstdint>

#define BB 16
#define HH 48
#define WWD 48
#define CC 128
#define NHH 8
#define SSW 8
#define LL (HH*WWD)
#define HD (CC/NHH)          // 16
#define NWIN (WWD/SSW)       // 6
#define SEQ (HH*SSW)         // 384

// scratch (no allocations allowed)
__device__ float g_pooled[BB*9*CC];
__device__ float g_w[BB*CC*9];
__device__ float g_bias[BB*CC];

typedef unsigned long long ull;
typedef unsigned int u32;

__device__ __forceinline__ float ex2f(float x){
  float r; asm("ex2.approx.ftz.f32 %0,%1;" : "=f"(r) : "f"(x)); return r;
}
// pack {lo=f16(x), hi=f16(y)}
__device__ __forceinline__ u32 cvt_h2(float x, float y){
  u32 d; asm("cvt.rn.f16x2.f32 %0,%1,%2;" : "=r"(d) : "f"(y), "f"(x)); return d;
}
__device__ __forceinline__ void mma_f16(float (&d)[4], const u32 (&a)[4], u32 b0, u32 b1){
  asm volatile("mma.sync.aligned.m16n8k16.row.col.f32.f16.f16.f32 "
    "{%0,%1,%2,%3}, {%4,%5,%6,%7}, {%8,%9}, {%0,%1,%2,%3};"
    : "+f"(d[0]), "+f"(d[1]), "+f"(d[2]), "+f"(d[3])
    : "r"(a[0]), "r"(a[1]), "r"(a[2]), "r"(a[3]), "r"(b0), "r"(b1));
}

// ---------------------------------------------------------------------------
// Kernel 1: adaptive avg pool to 3x3 (uniform 16x16 block means)
// ---------------------------------------------------------------------------
__global__ void pool_kernel(const float* __restrict__ v){
  const int bin = blockIdx.x, b = blockIdx.y, ch = blockIdx.z;
  const int ky = bin / 3, kx = bin - ky*3;
  const int tid = threadIdx.x;
  const int c4 = tid & 15, part = tid >> 4;
  const int row = part >> 1, wh = part & 1;
  const int cg = ch*16 + c4;
  const float4* vb = (const float4*)(v + (size_t)b*LL*CC);
  const int h = ky*16 + row;
  const float4* p = vb + (size_t)(h*WWD + kx*16 + wh*8)*(CC/4) + cg;
  float4 s = make_float4(0.f,0.f,0.f,0.f);
  #pragma unroll
  for (int ww = 0; ww < 8; ww++){
    float4 t = p[ww*(CC/4)];
    s.x += t.x; s.y += t.y; s.z += t.z; s.w += t.w;
  }
  __shared__ float4 red[512];
  red[tid] = s; __syncthreads();
  #pragma unroll
  for (int off = 256; off >= 16; off >>= 1){
    if (tid < off){
      float4 o = red[tid+off];
      s.x += o.x; s.y += o.y; s.z += o.z; s.w += o.w;
      red[tid] = s;
    }
    __syncthreads();
  }
  if (tid < 16){
    s.x *= (1.f/256.f); s.y *= (1.f/256.f); s.z *= (1.f/256.f); s.w *= (1.f/256.f);
    ((float4*)g_pooled)[(b*9 + bin)*32 + ch*16 + tid] = s;
  }
}

// ---------------------------------------------------------------------------
// Kernel 2: proj MLP, one (batch, position) per block; pos 9 = global mean
// ---------------------------------------------------------------------------
__global__ void proj_kernel(const float* __restrict__ p1w, const float* __restrict__ p1b,
                            const float* __restrict__ bng, const float* __restrict__ bnb,
                            const float* __restrict__ bnm, const float* __restrict__ bnv,
                            const float* __restrict__ p2w, const float* __restrict__ p2b,
                            const float* __restrict__ dynw, const float* __restrict__ dynb){
  const int b = blockIdx.x, pos = blockIdx.y;
  const int tid = threadIdx.x;
  __shared__ float prow[128];
  __shared__ float act[32];

  {
    float s;
    if (pos < 9) s = g_pooled[(b*9 + pos)*CC + tid];
    else {
      s = 0.f;
      #pragma unroll
      for (int qq = 0; qq < 9; qq++) s += g_pooled[(b*9 + qq)*CC + tid];
      s *= (1.f/9.f);
    }
    prow[tid] = s;
  }
  __syncthreads();

  if (tid < 32){
    const int o = tid;
    float s = p1b[o];
    const float4* w = (const float4*)(p1w + o*CC);
    #pragma unroll 8
    for (int i = 0; i < 32; i++){
      float4 ww = w[i];
      s += ww.x*prow[4*i] + ww.y*prow[4*i+1] + ww.z*prow[4*i+2] + ww.w*prow[4*i+3];
    }
    float inv = rsqrtf(bnv[o] + 1e-5f);
    s = (s - bnm[o]) * (inv * bng[o]) + bnb[o];
    s = 0.5f * s * (1.f + erff(s * 0.70710678118654752f));
    act[o] = s;
  }
  __syncthreads();

  {
    const int c = tid;
    float y[4];
    #pragma unroll
    for (int g = 0; g < 4; g++){
      int oc = g*CC + c;
      float s = p2b[oc];
      const float4* w = (const float4*)(p2w + oc*32);
      #pragma unroll
      for (int i = 0; i < 8; i++){
        float4 ww = w[i];
        s += ww.x*act[4*i] + ww.y*act[4*i+1] + ww.z*act[4*i+2] + ww.w*act[4*i+3];
      }
      y[g] = s;
    }
    float m = fmaxf(fmaxf(y[0],y[1]), fmaxf(y[2],y[3]));
    float e0 = expf(y[0]-m), e1 = expf(y[1]-m), e2 = expf(y[2]-m), e3 = expf(y[3]-m);
    float rs = 1.f / (e0+e1+e2+e3);
    if (pos < 9){
      float wv = e0*dynw[(0*CC+c)*9+pos] + e1*dynw[(1*CC+c)*9+pos]
               + e2*dynw[(2*CC+c)*9+pos] + e3*dynw[(3*CC+c)*9+pos];
      g_w[(b*CC + c)*9 + pos] = wv * rs;
    } else {
      float bv = e0*dynb[0*CC+c] + e1*dynb[1*CC+c] + e2*dynb[2*CC+c] + e3*dynb[3*CC+c];
      g_bias[b*CC + c] = bv * rs;
    }
  }
}

// ---------------------------------------------------------------------------
// Kernel 3: tensor-core attention, fp16 single-MMA, 3 CTAs/SM (6 warps/SMSP)
// Halo stored fp16 (conv via HFMA2) to shrink smem; single S buffer to fit
// the 85-reg cap. Warp-skewed key ring retained.
// grid (8 heads, 6 wblks, 16 batches), 256 threads = 8 warps x 48 queries
// ---------------------------------------------------------------------------
#define KOFF    0
#define VOFF    12288
#define VSTRIDE 800
#define HOFF    25088       // halo fp16: 50*10*16*2 = 16000
#define W2_OFF  41088       // 72 * 4B (f16x2 per tap per ch-pair)
#define B2_OFF  41376       // 8 * 4B
#define SMEM_SZ 41472

__global__ void __launch_bounds__(256, 3)
attn_kernel(const float* __restrict__ q, const float* __restrict__ k,
            const float* __restrict__ v, float* __restrict__ out){
  extern __shared__ char smem[];
  char* sK  = smem + KOFF;
  char* sVt = smem + VOFF;
  __half2* haloh = (__half2*)(smem + HOFF);   // [50*10][8] half2
  __half2* sW2 = (__half2*)(smem + W2_OFF);   // [9][8]
  __half2* sB2 = (__half2*)(smem + B2_OFF);   // [8]

  const int head = blockIdx.x, wblk = blockIdx.y, b = blockIdx.z;
  const int c0 = head*HD;
  const int wb0 = wblk*SSW;
  const int tid = threadIdx.x;
  const int wid = tid >> 5, lane = tid & 31;
  const int grp = lane >> 2, tig = lane & 3;
  const size_t bbase = (size_t)b*LL*CC;

  // ---- fill K (fp16, slot-permuted) ----
  for (int i = tid; i < SEQ*4; i += 256){
    int key = i >> 2, dq = (i & 3)*4;
    int hj = key >> 3, wj = key & 7;
    float4 kv = *(const float4*)(k + bbase + (size_t)(hj*WWD + wb0 + wj)*CC + c0 + dq);
    int j0 = dq >> 1;                         // pair index 0,2,4,6
    int s0 = (j0 < 4) ? 2*j0 : 2*j0 - 7;
    int s1 = (j0+1 < 4) ? 2*(j0+1) : 2*(j0+1) - 7;
    u32* row = (u32*)(sK + key*32);
    row[s0] = cvt_h2(kv.x, kv.y);
    row[s1] = cvt_h2(kv.z, kv.w);
  }
  // ---- fill Vt (fp16 transposed, slot-permuted per 16-key block) ----
  for (int i = tid; i < SEQ*4; i += 256){
    int key = i >> 2, dq = (i & 3)*4;
    int hj = key >> 3, wj = key & 7;
    float4 vv = *(const float4*)(v + bbase + (size_t)(hj*WWD + wb0 + wj)*CC + c0 + dq);
    float vals[4] = {vv.x, vv.y, vv.z, vv.w};
    int blk = key >> 4, r = key & 15;
    int pr = r >> 1;
    int slot = (r < 8) ? 2*pr : 2*(pr-4)+1;
    int byte = blk*32 + slot*4 + (r & 1)*2;
    #pragma unroll
    for (int d = 0; d < 4; d++)
      *(__half*)(sVt + (dq+d)*VSTRIDE + byte) = __float2half(vals[d]);
  }
  // ---- fill fp16 halo for conv ----
  for (int i = tid; i < 50*10*4; i += 256){
    int pos = i >> 2, dq = i & 3;
    int hh = pos / 10, ww = pos - hh*10;
    int gh = hh - 1, gw = wb0 + ww - 1;
    float4 val = make_float4(0.f,0.f,0.f,0.f);
    if (gh >= 0 && gh < HH && gw >= 0 && gw < WWD)
      val = *(const float4*)(v + bbase + (size_t)(gh*WWD + gw)*CC + c0 + dq*4);
    haloh[pos*8 + dq*2]     = __floats2half2_rn(val.x, val.y);
    haloh[pos*8 + dq*2 + 1] = __floats2half2_rn(val.z, val.w);
  }
  if (tid < 72){
    int t = tid >> 3, i = tid & 7;
    sW2[t*8+i] = __floats2half2_rn(g_w[(b*CC + c0 + 2*i)*9 + t],
                                   g_w[(b*CC + c0 + 2*i+1)*9 + t]);
  }
  if (tid < 8)
    sB2[tid] = __floats2half2_rn(g_bias[b*CC + c0 + 2*tid],
                                 g_bias[b*CC + c0 + 2*tid+1]);

  // ---- Q fragments (scaled fp16) ----
  const float SCL = 0.36067376022224085f;  // 0.25 * log2(e)
  u32 aq[3][4];
  #pragma unroll
  for (int mf = 0; mf < 3; mf++){
    #pragma unroll
    for (int rs = 0; rs < 2; rs++){
      int m = wid*48 + mf*16 + grp + rs*8;     // query 0..383
      int hl = m >> 3, w = m & 7;
      const float* qr = q + bbase + (size_t)(hl*WWD + wb0 + w)*CC + c0;
      float2 qa = *(const float2*)(qr + 2*tig);
      float2 qb = *(const float2*)(qr + 2*tig + 8);
      aq[mf][rs]   = cvt_h2(qa.x*SCL, qa.y*SCL);
      aq[mf][rs+2] = cvt_h2(qb.x*SCL, qb.y*SCL);
    }
  }
  __syncthreads();

  float o[3][2][4];
  #pragma unroll
  for (int mf = 0; mf < 3; mf++)
    #pragma unroll
    for (int cn = 0; cn < 2; cn++)
      #pragma unroll
      for (int r = 0; r < 4; r++) o[mf][cn][r] = 0.f;
  float ls[3][2];
  #pragma unroll
  for (int mf = 0; mf < 3; mf++){ ls[mf][0] = 0.f; ls[mf][1] = 0.f; }

  // ---- warp-skewed mainloop over the 24-step key ring (single S buffer;
  //      cross-warp occupancy provides the pipe overlap) ----
  int tcur = wid*3;
  #pragma unroll 4
  for (int it = 0; it < 24; it++){
    const int t_ = tcur;
    tcur = (tcur + 1 < 24) ? tcur + 1 : 0;
    uint2 kh0 = *(const uint2*)(sK + (t_*16 + grp)*32 + tig*8);
    uint2 kh1 = *(const uint2*)(sK + (t_*16 + 8 + grp)*32 + tig*8);
    uint2 vv0 = *(const uint2*)(sVt + (grp)*VSTRIDE + t_*32 + tig*8);
    uint2 vv1 = *(const uint2*)(sVt + (8 + grp)*VSTRIDE + t_*32 + tig*8);
    #pragma unroll
    for (int mf = 0; mf < 3; mf++){
      float s0[4] = {0.f,0.f,0.f,0.f};
      float s1[4] = {0.f,0.f,0.f,0.f};
      mma_f16(s0, aq[mf], kh0.x, kh0.y);
      mma_f16(s1, aq[mf], kh1.x, kh1.y);
      s0[0] = ex2f(s0[0]); s0[1] = ex2f(s0[1]);
      s0[2] = ex2f(s0[2]); s0[3] = ex2f(s0[3]);
      s1[0] = ex2f(s1[0]); s1[1] = ex2f(s1[1]);
      s1[2] = ex2f(s1[2]); s1[3] = ex2f(s1[3]);
      ls[mf][0] += (s0[0] + s0[1]) + (s1[0] + s1[1]);
      ls[mf][1] += (s0[2] + s0[3]) + (s1[2] + s1[3]);
      u32 ph[4];
      ph[0] = cvt_h2(s0[0], s0[1]);
      ph[1] = cvt_h2(s0[2], s0[3]);
      ph[2] = cvt_h2(s1[0], s1[1]);
      ph[3] = cvt_h2(s1[2], s1[3]);
      mma_f16(o[mf][0], ph, vv0.x, vv0.y);
      mma_f16(o[mf][1], ph, vv1.x, vv1.y);
    }
  }

  // reduce lsum across the 4 threads of each row group
  #pragma unroll
  for (int mf = 0; mf < 3; mf++){
    #pragma unroll
    for (int rs = 0; rs < 2; rs++){
      float r = ls[mf][rs];
      r += __shfl_xor_sync(0xffffffffu, r, 1);
      r += __shfl_xor_sync(0xffffffffu, r, 2);
      ls[mf][rs] = 1.0f / r;
    }
  }

  // ---- epilogue: HFMA2 conv + bias + normalize + store ----
  #pragma unroll
  for (int mf = 0; mf < 3; mf++){
    #pragma unroll
    for (int rs = 0; rs < 2; rs++){
      int m = wid*48 + mf*16 + grp + rs*8;
      int hl = m >> 3, w = m & 7;
      float rinv = ls[mf][rs];
      float* orow = out + bbase + (size_t)(hl*WWD + wb0 + w)*CC + c0;
      #pragma unroll
      for (int cn = 0; cn < 2; cn++){
        int cp = cn*4 + tig;     // channel pair index
        __half2 acc = sB2[cp];
        #pragma unroll
        for (int t = 0; t < 9; t++){
          int dy = t/3, dx = t - dy*3;
          acc = __hfma2(sW2[t*8+cp], haloh[((hl+dy)*10 + (w+dx))*8 + cp], acc);
        }
        float2 cv = __half22float2(acc);
        float2 res;
        res.x = o[mf][cn][rs*2]   * rinv + cv.x;
        res.y = o[mf][cn][rs*2+1] * rinv + cv.y;
        *(float2*)(orow + cn*8 + 2*tig) = res;
      }
    }
  }
}

// ---------------------------------------------------------------------------
extern "C" void kernel_launch(void* const* d_in, const int* in_sizes, int n_in,
                              void* d_out, int out_size){
  const float* q    = (const float*)d_in[0];
  const float* k    = (const float*)d_in[1];
  const float* v    = (const float*)d_in[2];
  const float* p1w  = (const float*)d_in[3];
  const float* p1b  = (const float*)d_in[4];
  const float* bng  = (const float*)d_in[5];
  const float* bnb  = (const float*)d_in[6];
  const float* bnm  = (const float*)d_in[7];
  const float* bnv  = (const float*)d_in[8];
  const float* p2w  = (const float*)d_in[9];
  const float* p2b  = (const float*)d_in[10];
  const float* dynw = (const float*)d_in[11];
  const float* dynb = (const float*)d_in[12];
  float* out = (float*)d_out;

  cudaFuncSetAttribute(attn_kernel, cudaFuncAttributeMaxDynamicSharedMemorySize, SMEM_SZ);

  pool_kernel<<<dim3(9, BB, 2), 512>>>(v);
  proj_kernel<<<dim3(BB, 10), 128>>>(p1w, p1b, bng, bnb, bnm, bnv, p2w, p2b, dynw, dynb);
  attn_kernel<<<dim3(NHH, NWIN, BB), 256, SMEM_SZ>>>(q, k, v, out);
}

// round 10
// speedup vs baseline: 6.0211x; 1.0409x over previous
#include <cuda_runtime.h>
#include <cuda_bf16.h>
#include <cuda_fp16.h>
#include <cstdint>

#define BB 16
#define HH 48
#define WWD 48
#define CC 128
#define NHH 8
#define SSW 8
#define LL (HH*WWD)
#define HD (CC/NHH)          // 16
#define NWIN (WWD/SSW)       // 6
#define SEQ (HH*SSW)         // 384

// scratch (no allocations allowed)
__device__ float g_pooled[BB*9*CC];
__device__ float g_w[BB*CC*9];
__device__ float g_bias[BB*CC];

typedef unsigned long long ull;
typedef unsigned int u32;

// pack {lo=f16(x), hi=f16(y)}
__device__ __forceinline__ u32 cvt_h2(float x, float y){
  u32 d; asm("cvt.rn.f16x2.f32 %0,%1,%2;" : "=r"(d) : "f"(y), "f"(x)); return d;
}
__device__ __forceinline__ u32 ex2h2(u32 x){
  u32 d; asm("ex2.approx.f16x2 %0,%1;" : "=r"(d) : "r"(x)); return d;
}
__device__ __forceinline__ void mma_f16(float (&d)[4], const u32 (&a)[4], u32 b0, u32 b1){
  asm volatile("mma.sync.aligned.m16n8k16.row.col.f32.f16.f16.f32 "
    "{%0,%1,%2,%3}, {%4,%5,%6,%7}, {%8,%9}, {%0,%1,%2,%3};"
    : "+f"(d[0]), "+f"(d[1]), "+f"(d[2]), "+f"(d[3])
    : "r"(a[0]), "r"(a[1]), "r"(a[2]), "r"(a[3]), "r"(b0), "r"(b1));
}

// ---------------------------------------------------------------------------
// Kernel 1: adaptive avg pool to 3x3 (uniform 16x16 block means)
// ---------------------------------------------------------------------------
__global__ void pool_kernel(const float* __restrict__ v){
  const int bin = blockIdx.x, b = blockIdx.y, ch = blockIdx.z;
  const int ky = bin / 3, kx = bin - ky*3;
  const int tid = threadIdx.x;
  const int c4 = tid & 15, part = tid >> 4;
  const int row = part >> 1, wh = part & 1;
  const int cg = ch*16 + c4;
  const float4* vb = (const float4*)(v + (size_t)b*LL*CC);
  const int h = ky*16 + row;
  const float4* p = vb + (size_t)(h*WWD + kx*16 + wh*8)*(CC/4) + cg;
  float4 s = make_float4(0.f,0.f,0.f,0.f);
  #pragma unroll
  for (int ww = 0; ww < 8; ww++){
    float4 t = p[ww*(CC/4)];
    s.x += t.x; s.y += t.y; s.z += t.z; s.w += t.w;
  }
  __shared__ float4 red[512];
  red[tid] = s; __syncthreads();
  #pragma unroll
  for (int off = 256; off >= 16; off >>= 1){
    if (tid < off){
      float4 o = red[tid+off];
      s.x += o.x; s.y += o.y; s.z += o.z; s.w += o.w;
      red[tid] = s;
    }
    __syncthreads();
  }
  if (tid < 16){
    s.x *= (1.f/256.f); s.y *= (1.f/256.f); s.z *= (1.f/256.f); s.w *= (1.f/256.f);
    ((float4*)g_pooled)[(b*9 + bin)*32 + ch*16 + tid] = s;
  }
}

// ---------------------------------------------------------------------------
// Kernel 2: proj MLP, one (batch, position) per block; pos 9 = global mean
// ---------------------------------------------------------------------------
__global__ void proj_kernel(const float* __restrict__ p1w, const float* __restrict__ p1b,
                            const float* __restrict__ bng, const float* __restrict__ bnb,
                            const float* __restrict__ bnm, const float* __restrict__ bnv,
                            const float* __restrict__ p2w, const float* __restrict__ p2b,
                            const float* __restrict__ dynw, const float* __restrict__ dynb){
  const int b = blockIdx.x, pos = blockIdx.y;
  const int tid = threadIdx.x;
  __shared__ float prow[128];
  __shared__ float act[32];

  {
    float s;
    if (pos < 9) s = g_pooled[(b*9 + pos)*CC + tid];
    else {
      s = 0.f;
      #pragma unroll
      for (int qq = 0; qq < 9; qq++) s += g_pooled[(b*9 + qq)*CC + tid];
      s *= (1.f/9.f);
    }
    prow[tid] = s;
  }
  __syncthreads();

  if (tid < 32){
    const int o = tid;
    float s = p1b[o];
    const float4* w = (const float4*)(p1w + o*CC);
    #pragma unroll 8
    for (int i = 0; i < 32; i++){
      float4 ww = w[i];
      s += ww.x*prow[4*i] + ww.y*prow[4*i+1] + ww.z*prow[4*i+2] + ww.w*prow[4*i+3];
    }
    float inv = rsqrtf(bnv[o] + 1e-5f);
    s = (s - bnm[o]) * (inv * bng[o]) + bnb[o];
    s = 0.5f * s * (1.f + erff(s * 0.70710678118654752f));
    act[o] = s;
  }
  __syncthreads();

  {
    const int c = tid;
    float y[4];
    #pragma unroll
    for (int g = 0; g < 4; g++){
      int oc = g*CC + c;
      float s = p2b[oc];
      const float4* w = (const float4*)(p2w + oc*32);
      #pragma unroll
      for (int i = 0; i < 8; i++){
        float4 ww = w[i];
        s += ww.x*act[4*i] + ww.y*act[4*i+1] + ww.z*act[4*i+2] + ww.w*act[4*i+3];
      }
      y[g] = s;
    }
    float m = fmaxf(fmaxf(y[0],y[1]), fmaxf(y[2],y[3]));
    float e0 = expf(y[0]-m), e1 = expf(y[1]-m), e2 = expf(y[2]-m), e3 = expf(y[3]-m);
    float rs = 1.f / (e0+e1+e2+e3);
    if (pos < 9){
      float wv = e0*dynw[(0*CC+c)*9+pos] + e1*dynw[(1*CC+c)*9+pos]
               + e2*dynw[(2*CC+c)*9+pos] + e3*dynw[(3*CC+c)*9+pos];
      g_w[(b*CC + c)*9 + pos] = wv * rs;
    } else {
      float bv = e0*dynb[0*CC+c] + e1*dynb[1*CC+c] + e2*dynb[2*CC+c] + e3*dynb[3*CC+c];
      g_bias[b*CC + c] = bv * rs;
    }
  }
}

// ---------------------------------------------------------------------------
// Kernel 3: tensor-core attention, fp16 single-MMA, f16x2 ex2 (half MUFU),
// 3 CTAs/SM. Unified K/V layouts: one LDS.128 per lane per step for each.
//   K: [24 steps][8 grp][4 tig] x 16B = {kh0(8B) key=grp | kh1(8B) key=8+grp}
//   V: [24 steps][8 grp][4 tig] x 16B = {ch=grp(8B) | ch=8+grp(8B)}
// grid (8 heads, 6 wblks, 16 batches), 256 threads = 8 warps x 48 queries
// ---------------------------------------------------------------------------
#define KOFF    0
#define VOFF    12288
#define HOFF    24576       // halo fp16: 50*10*16*2 = 16000
#define W2_OFF  40576
#define B2_OFF  40864
#define SMEM_SZ 40896

__global__ void __launch_bounds__(256, 3)
attn_kernel(const float* __restrict__ q, const float* __restrict__ k,
            const float* __restrict__ v, float* __restrict__ out){
  extern __shared__ char smem[];
  char* sK  = smem + KOFF;
  char* sV  = smem + VOFF;
  __half2* haloh = (__half2*)(smem + HOFF);   // [50*10][8] half2
  __half2* sW2 = (__half2*)(smem + W2_OFF);   // [9][8]
  __half2* sB2 = (__half2*)(smem + B2_OFF);   // [8]

  const int head = blockIdx.x, wblk = blockIdx.y, b = blockIdx.z;
  const int c0 = head*HD;
  const int wb0 = wblk*SSW;
  const int tid = threadIdx.x;
  const int wid = tid >> 5, lane = tid & 31;
  const int grp = lane >> 2, tig = lane & 3;
  const size_t bbase = (size_t)b*LL*CC;

  // ---- fill K (fp16, frag-packed: lane 16B = kh0|kh1) ----
  for (int i = tid; i < SEQ*4; i += 256){
    int key = i >> 2, dq = (i & 3)*4;
    int hj = key >> 3, wj = key & 7;
    float4 kv = *(const float4*)(k + bbase + (size_t)(hj*WWD + wb0 + wj)*CC + c0 + dq);
    u32 h0 = cvt_h2(kv.x, kv.y);
    u32 h1 = cvt_h2(kv.z, kv.w);
    int j0 = dq >> 1;                         // pair index 0,2,4,6
    int s0 = (j0 < 4) ? 2*j0 : 2*j0 - 7;
    int s1 = (j0+1 < 4) ? 2*(j0+1) : 2*(j0+1) - 7;
    int p0 = s0*4, p1 = s1*4;
    int step = key >> 4, r = key & 15;
    char* base = sK + step*512 + (r & 7)*64 + ((r >= 8) ? 8 : 0);
    *(u32*)(base + (p0 >> 3)*16 + (p0 & 7)) = h0;
    *(u32*)(base + (p1 >> 3)*16 + (p1 & 7)) = h1;
  }
  // ---- fill V (fp16 transposed, frag-packed: lane 16B = ch grp | ch 8+grp) ----
  for (int i = tid; i < SEQ*4; i += 256){
    int key = i >> 2, dq = (i & 3)*4;
    int hj = key >> 3, wj = key & 7;
    float4 vv = *(const float4*)(v + bbase + (size_t)(hj*WWD + wb0 + wj)*CC + c0 + dq);
    float vals[4] = {vv.x, vv.y, vv.z, vv.w};
    int blk = key >> 4, r = key & 15;
    int pr = r >> 1;
    int slot = (r < 8) ? 2*pr : 2*(pr-4)+1;
    int q0 = slot*4 + (r & 1)*2;
    char* base = sV + blk*512 + (q0 >> 3)*16 + (q0 & 7);
    #pragma unroll
    for (int d = 0; d < 4; d++){
      int ch = dq + d;
      *(__half*)(base + (ch & 7)*64 + ((ch >= 8) ? 8 : 0)) = __float2half(vals[d]);
    }
  }
  // ---- fill fp16 halo for conv ----
  for (int i = tid; i < 50*10*4; i += 256){
    int pos = i >> 2, dq = i & 3;
    int hh = pos / 10, ww = pos - hh*10;
    int gh = hh - 1, gw = wb0 + ww - 1;
    float4 val = make_float4(0.f,0.f,0.f,0.f);
    if (gh >= 0 && gh < HH && gw >= 0 && gw < WWD)
      val = *(const float4*)(v + bbase + (size_t)(gh*WWD + gw)*CC + c0 + dq*4);
    haloh[pos*8 + dq*2]     = __floats2half2_rn(val.x, val.y);
    haloh[pos*8 + dq*2 + 1] = __floats2half2_rn(val.z, val.w);
  }
  if (tid < 72){
    int t = tid >> 3, i = tid & 7;
    sW2[t*8+i] = __floats2half2_rn(g_w[(b*CC + c0 + 2*i)*9 + t],
                                   g_w[(b*CC + c0 + 2*i+1)*9 + t]);
  }
  if (tid < 8)
    sB2[tid] = __floats2half2_rn(g_bias[b*CC + c0 + 2*tid],
                                 g_bias[b*CC + c0 + 2*tid+1]);

  // ---- Q fragments (scaled fp16) ----
  const float SCL = 0.36067376022224085f;  // 0.25 * log2(e)
  u32 aq[3][4];
  #pragma unroll
  for (int mf = 0; mf < 3; mf++){
    #pragma unroll
    for (int rs = 0; rs < 2; rs++){
      int m = wid*48 + mf*16 + grp + rs*8;     // query 0..383
      int hl = m >> 3, w = m & 7;
      const float* qr = q + bbase + (size_t)(hl*WWD + wb0 + w)*CC + c0;
      float2 qa = *(const float2*)(qr + 2*tig);
      float2 qb = *(const float2*)(qr + 2*tig + 8);
      aq[mf][rs]   = cvt_h2(qa.x*SCL, qa.y*SCL);
      aq[mf][rs+2] = cvt_h2(qb.x*SCL, qb.y*SCL);
    }
  }
  __syncthreads();

  float o[3][2][4];
  #pragma unroll
  for (int mf = 0; mf < 3; mf++)
    #pragma unroll
    for (int cn = 0; cn < 2; cn++)
      #pragma unroll
      for (int r = 0; r < 4; r++) o[mf][cn][r] = 0.f;
  float ls[3][2];
  #pragma unroll
  for (int mf = 0; mf < 3; mf++){ ls[mf][0] = 0.f; ls[mf][1] = 0.f; }

  // ---- warp-skewed mainloop over the 24-step key ring ----
  int tcur = wid*3;
  #pragma unroll 4
  for (int it = 0; it < 24; it++){
    const int t_ = tcur;
    tcur = (tcur + 1 < 24) ? tcur + 1 : 0;
    const int lbase = t_*512 + grp*64 + tig*16;
    uint4 kk = *(const uint4*)(sK + lbase);
    uint4 vk = *(const uint4*)(sV + lbase);
    #pragma unroll
    for (int mf = 0; mf < 3; mf++){
      float s0[4] = {0.f,0.f,0.f,0.f};
      float s1[4] = {0.f,0.f,0.f,0.f};
      mma_f16(s0, aq[mf], kk.x, kk.y);
      mma_f16(s1, aq[mf], kk.z, kk.w);
      u32 pa[4];
      pa[0] = ex2h2(cvt_h2(s0[0], s0[1]));
      pa[1] = ex2h2(cvt_h2(s0[2], s0[3]));
      pa[2] = ex2h2(cvt_h2(s1[0], s1[1]));
      pa[3] = ex2h2(cvt_h2(s1[2], s1[3]));
      __half2 t0 = __hadd2(*(__half2*)&pa[0], *(__half2*)&pa[2]);
      __half2 t1 = __hadd2(*(__half2*)&pa[1], *(__half2*)&pa[3]);
      float2 f0 = __half22float2(t0); ls[mf][0] += f0.x + f0.y;
      float2 f1 = __half22float2(t1); ls[mf][1] += f1.x + f1.y;
      mma_f16(o[mf][0], pa, vk.x, vk.y);
      mma_f16(o[mf][1], pa, vk.z, vk.w);
    }
  }

  // reduce lsum across the 4 threads of each row group
  #pragma unroll
  for (int mf = 0; mf < 3; mf++){
    #pragma unroll
    for (int rs = 0; rs < 2; rs++){
      float r = ls[mf][rs];
      r += __shfl_xor_sync(0xffffffffu, r, 1);
      r += __shfl_xor_sync(0xffffffffu, r, 2);
      ls[mf][rs] = 1.0f / r;
    }
  }

  // ---- epilogue: HFMA2 conv + bias + normalize + store ----
  #pragma unroll
  for (int mf = 0; mf < 3; mf++){
    #pragma unroll
    for (int rs = 0; rs < 2; rs++){
      int m = wid*48 + mf*16 + grp + rs*8;
      int hl = m >> 3, w = m & 7;
      float rinv = ls[mf][rs];
      float* orow = out + bbase + (size_t)(hl*WWD + wb0 + w)*CC + c0;
      #pragma unroll
      for (int cn = 0; cn < 2; cn++){
        int cp = cn*4 + tig;     // channel pair index
        __half2 acc = sB2[cp];
        #pragma unroll
        for (int t = 0; t < 9; t++){
          int dy = t/3, dx = t - dy*3;
          acc = __hfma2(sW2[t*8+cp], haloh[((hl+dy)*10 + (w+dx))*8 + cp], acc);
        }
        float2 cv = __half22float2(acc);
        float2 res;
        res.x = o[mf][cn][rs*2]   * rinv + cv.x;
        res.y = o[mf][cn][rs*2+1] * rinv + cv.y;
        *(float2*)(orow + cn*8 + 2*tig) = res;
      }
    }
  }
}

// ---------------------------------------------------------------------------
extern "C" void kernel_launch(void* const* d_in, const int* in_sizes, int n_in,
                              void* d_out, int out_size){
  const float* q    = (const float*)d_in[0];
  const float* k    = (const float*)d_in[1];
  const float* v    = (const float*)d_in[2];
  const float* p1w  = (const float*)d_in[3];
  const float* p1b  = (const float*)d_in[4];
  const float* bng  = (const float*)d_in[5];
  const float* bnb  = (const float*)d_in[6];
  const float* bnm  = (const float*)d_in[7];
  const float* bnv  = (const float*)d_in[8];
  const float* p2w  = (const float*)d_in[9];
  const float* p2b  = (const float*)d_in[10];
  const float* dynw = (const float*)d_in[11];
  const float* dynb = (const float*)d_in[12];
  float* out = (float*)d_out;

  cudaFuncSetAttribute(attn_kernel, cudaFuncAttributeMaxDynamicSharedMemorySize, SMEM_SZ);

  pool_kernel<<<dim3(9, BB, 2), 512>>>(v);
  proj_kernel<<<dim3(BB, 10), 128>>>(p1w, p1b, bng, bnb, bnm, bnv, p2w, p2b, dynw, dynb);
  attn_kernel<<<dim3(NHH, NWIN, BB), 256, SMEM_SZ>>>(q, k, v, out);
}

// round 11
// speedup vs baseline: 6.4963x; 1.0789x over previous
#include <cuda_runtime.h>
#include <cuda_bf16.h>
#include <cuda_fp16.h>
#include <cstdint>

#define BB 16
#define HH 48
#define WWD 48
#define CC 128
#define NHH 8
#define SSW 8
#define LL (HH*WWD)
#define HD (CC/NHH)          // 16
#define NWIN (WWD/SSW)       // 6
#define SEQ (HH*SSW)         // 384

// scratch (no allocations allowed)
__device__ float g_pooled[BB*9*CC];
__device__ float g_w[BB*CC*9];
__device__ float g_bias[BB*CC];

typedef unsigned long long ull;
typedef unsigned int u32;

// pack {lo=f16(x), hi=f16(y)}
__device__ __forceinline__ u32 cvt_h2(float x, float y){
  u32 d; asm("cvt.rn.f16x2.f32 %0,%1,%2;" : "=r"(d) : "f"(y), "f"(x)); return d;
}
__device__ __forceinline__ u32 ex2h2(u32 x){
  u32 d; asm("ex2.approx.f16x2 %0,%1;" : "=r"(d) : "r"(x)); return d;
}
// fp32-accumulate f16 MMA
__device__ __forceinline__ void mma_f16(float (&d)[4], const u32 (&a)[4], u32 b0, u32 b1){
  asm volatile("mma.sync.aligned.m16n8k16.row.col.f32.f16.f16.f32 "
    "{%0,%1,%2,%3}, {%4,%5,%6,%7}, {%8,%9}, {%0,%1,%2,%3};"
    : "+f"(d[0]), "+f"(d[1]), "+f"(d[2]), "+f"(d[3])
    : "r"(a[0]), "r"(a[1]), "r"(a[2]), "r"(a[3]), "r"(b0), "r"(b1));
}
// fp16-accumulate f16 MMA, separate zero C (no accumulator zeroing in loop)
__device__ __forceinline__ void mma_f16h(u32& d0, u32& d1, const u32 (&a)[4],
                                         u32 b0, u32 b1, u32 zc){
  asm volatile("mma.sync.aligned.m16n8k16.row.col.f16.f16.f16.f16 "
    "{%0,%1}, {%2,%3,%4,%5}, {%6,%7}, {%8,%9};"
    : "=r"(d0), "=r"(d1)
    : "r"(a[0]), "r"(a[1]), "r"(a[2]), "r"(a[3]), "r"(b0), "r"(b1),
      "r"(zc), "r"(zc));
}

// ---------------------------------------------------------------------------
// Kernel 1: adaptive avg pool to 3x3 (uniform 16x16 block means)
// ---------------------------------------------------------------------------
__global__ void pool_kernel(const float* __restrict__ v){
  const int bin = blockIdx.x, b = blockIdx.y, ch = blockIdx.z;
  const int ky = bin / 3, kx = bin - ky*3;
  const int tid = threadIdx.x;
  const int c4 = tid & 15, part = tid >> 4;
  const int row = part >> 1, wh = part & 1;
  const int cg = ch*16 + c4;
  const float4* vb = (const float4*)(v + (size_t)b*LL*CC);
  const int h = ky*16 + row;
  const float4* p = vb + (size_t)(h*WWD + kx*16 + wh*8)*(CC/4) + cg;
  float4 s = make_float4(0.f,0.f,0.f,0.f);
  #pragma unroll
  for (int ww = 0; ww < 8; ww++){
    float4 t = p[ww*(CC/4)];
    s.x += t.x; s.y += t.y; s.z += t.z; s.w += t.w;
  }
  __shared__ float4 red[512];
  red[tid] = s; __syncthreads();
  #pragma unroll
  for (int off = 256; off >= 16; off >>= 1){
    if (tid < off){
      float4 o = red[tid+off];
      s.x += o.x; s.y += o.y; s.z += o.z; s.w += o.w;
      red[tid] = s;
    }
    __syncthreads();
  }
  if (tid < 16){
    s.x *= (1.f/256.f); s.y *= (1.f/256.f); s.z *= (1.f/256.f); s.w *= (1.f/256.f);
    ((float4*)g_pooled)[(b*9 + bin)*32 + ch*16 + tid] = s;
  }
}

// ---------------------------------------------------------------------------
// Kernel 2: proj MLP, one (batch, position) per block; pos 9 = global mean
// ---------------------------------------------------------------------------
__global__ void proj_kernel(const float* __restrict__ p1w, const float* __restrict__ p1b,
                            const float* __restrict__ bng, const float* __restrict__ bnb,
                            const float* __restrict__ bnm, const float* __restrict__ bnv,
                            const float* __restrict__ p2w, const float* __restrict__ p2b,
                            const float* __restrict__ dynw, const float* __restrict__ dynb){
  const int b = blockIdx.x, pos = blockIdx.y;
  const int tid = threadIdx.x;
  __shared__ float prow[128];
  __shared__ float act[32];

  {
    float s;
    if (pos < 9) s = g_pooled[(b*9 + pos)*CC + tid];
    else {
      s = 0.f;
      #pragma unroll
      for (int qq = 0; qq < 9; qq++) s += g_pooled[(b*9 + qq)*CC + tid];
      s *= (1.f/9.f);
    }
    prow[tid] = s;
  }
  __syncthreads();

  if (tid < 32){
    const int o = tid;
    float s = p1b[o];
    const float4* w = (const float4*)(p1w + o*CC);
    #pragma unroll 8
    for (int i = 0; i < 32; i++){
      float4 ww = w[i];
      s += ww.x*prow[4*i] + ww.y*prow[4*i+1] + ww.z*prow[4*i+2] + ww.w*prow[4*i+3];
    }
    float inv = rsqrtf(bnv[o] + 1e-5f);
    s = (s - bnm[o]) * (inv * bng[o]) + bnb[o];
    s = 0.5f * s * (1.f + erff(s * 0.70710678118654752f));
    act[o] = s;
  }
  __syncthreads();

  {
    const int c = tid;
    float y[4];
    #pragma unroll
    for (int g = 0; g < 4; g++){
      int oc = g*CC + c;
      float s = p2b[oc];
      const float4* w = (const float4*)(p2w + oc*32);
      #pragma unroll
      for (int i = 0; i < 8; i++){
        float4 ww = w[i];
        s += ww.x*act[4*i] + ww.y*act[4*i+1] + ww.z*act[4*i+2] + ww.w*act[4*i+3];
      }
      y[g] = s;
    }
    float m = fmaxf(fmaxf(y[0],y[1]), fmaxf(y[2],y[3]));
    float e0 = expf(y[0]-m), e1 = expf(y[1]-m), e2 = expf(y[2]-m), e3 = expf(y[3]-m);
    float rs = 1.f / (e0+e1+e2+e3);
    if (pos < 9){
      float wv = e0*dynw[(0*CC+c)*9+pos] + e1*dynw[(1*CC+c)*9+pos]
               + e2*dynw[(2*CC+c)*9+pos] + e3*dynw[(3*CC+c)*9+pos];
      g_w[(b*CC + c)*9 + pos] = wv * rs;
    } else {
      float bv = e0*dynb[0*CC+c] + e1*dynb[1*CC+c] + e2*dynb[2*CC+c] + e3*dynb[3*CC+c];
      g_bias[b*CC + c] = bv * rs;
    }
  }
}

// ---------------------------------------------------------------------------
// Kernel 3: tensor-core attention, issue-minimized mainloop:
//   QK with f16 accumulators (score already f16-rounded before ex2 anyway),
//   lsum via all-ones-B MMA (f32 accum; every D column = row sum of P so no
//   per-step scalar lsum code AND no final shuffle reduce).
//   9 instructions per mf per 16-key step: 2 QK + 4 ex2h2 + 2 PV + 1 LS.
// grid (8 heads, 6 wblks, 16 batches), 256 threads, 3 CTAs/SM
// ---------------------------------------------------------------------------
#define KOFF    0
#define VOFF    12288
#define HOFF    24576       // halo fp16: 50*10*16*2 = 16000
#define W2_OFF  40576
#define B2_OFF  40864
#define SMEM_SZ 40896
#define ONES16  0x3C003C00u

__global__ void __launch_bounds__(256, 3)
attn_kernel(const float* __restrict__ q, const float* __restrict__ k,
            const float* __restrict__ v, float* __restrict__ out){
  extern __shared__ char smem[];
  char* sK  = smem + KOFF;
  char* sV  = smem + VOFF;
  __half2* haloh = (__half2*)(smem + HOFF);   // [50*10][8] half2
  __half2* sW2 = (__half2*)(smem + W2_OFF);   // [9][8]
  __half2* sB2 = (__half2*)(smem + B2_OFF);   // [8]

  const int head = blockIdx.x, wblk = blockIdx.y, b = blockIdx.z;
  const int c0 = head*HD;
  const int wb0 = wblk*SSW;
  const int tid = threadIdx.x;
  const int wid = tid >> 5, lane = tid & 31;
  const int grp = lane >> 2, tig = lane & 3;
  const size_t bbase = (size_t)b*LL*CC;

  // ---- fill K (fp16, frag-packed: lane 16B = kh0|kh1) ----
  for (int i = tid; i < SEQ*4; i += 256){
    int key = i >> 2, dq = (i & 3)*4;
    int hj = key >> 3, wj = key & 7;
    float4 kv = *(const float4*)(k + bbase + (size_t)(hj*WWD + wb0 + wj)*CC + c0 + dq);
    u32 h0 = cvt_h2(kv.x, kv.y);
    u32 h1 = cvt_h2(kv.z, kv.w);
    int j0 = dq >> 1;                         // pair index 0,2,4,6
    int s0 = (j0 < 4) ? 2*j0 : 2*j0 - 7;
    int s1 = (j0+1 < 4) ? 2*(j0+1) : 2*(j0+1) - 7;
    int p0 = s0*4, p1 = s1*4;
    int step = key >> 4, r = key & 15;
    char* base = sK + step*512 + (r & 7)*64 + ((r >= 8) ? 8 : 0);
    *(u32*)(base + (p0 >> 3)*16 + (p0 & 7)) = h0;
    *(u32*)(base + (p1 >> 3)*16 + (p1 & 7)) = h1;
  }
  // ---- fill V (fp16 transposed, frag-packed: lane 16B = ch grp | ch 8+grp) ----
  for (int i = tid; i < SEQ*4; i += 256){
    int key = i >> 2, dq = (i & 3)*4;
    int hj = key >> 3, wj = key & 7;
    float4 vv = *(const float4*)(v + bbase + (size_t)(hj*WWD + wb0 + wj)*CC + c0 + dq);
    float vals[4] = {vv.x, vv.y, vv.z, vv.w};
    int blk = key >> 4, r = key & 15;
    int pr = r >> 1;
    int slot = (r < 8) ? 2*pr : 2*(pr-4)+1;
    int q0 = slot*4 + (r & 1)*2;
    char* base = sV + blk*512 + (q0 >> 3)*16 + (q0 & 7);
    #pragma unroll
    for (int d = 0; d < 4; d++){
      int ch = dq + d;
      *(__half*)(base + (ch & 7)*64 + ((ch >= 8) ? 8 : 0)) = __float2half(vals[d]);
    }
  }
  // ---- fill fp16 halo for conv ----
  for (int i = tid; i < 50*10*4; i += 256){
    int pos = i >> 2, dq = i & 3;
    int hh = pos / 10, ww = pos - hh*10;
    int gh = hh - 1, gw = wb0 + ww - 1;
    float4 val = make_float4(0.f,0.f,0.f,0.f);
    if (gh >= 0 && gh < HH && gw >= 0 && gw < WWD)
      val = *(const float4*)(v + bbase + (size_t)(gh*WWD + gw)*CC + c0 + dq*4);
    haloh[pos*8 + dq*2]     = __floats2half2_rn(val.x, val.y);
    haloh[pos*8 + dq*2 + 1] = __floats2half2_rn(val.z, val.w);
  }
  if (tid < 72){
    int t = tid >> 3, i = tid & 7;
    sW2[t*8+i] = __floats2half2_rn(g_w[(b*CC + c0 + 2*i)*9 + t],
                                   g_w[(b*CC + c0 + 2*i+1)*9 + t]);
  }
  if (tid < 8)
    sB2[tid] = __floats2half2_rn(g_bias[b*CC + c0 + 2*tid],
                                 g_bias[b*CC + c0 + 2*tid+1]);

  // ---- Q fragments (scaled fp16) ----
  const float SCL = 0.36067376022224085f;  // 0.25 * log2(e)
  u32 aq[3][4];
  #pragma unroll
  for (int mf = 0; mf < 3; mf++){
    #pragma unroll
    for (int rs = 0; rs < 2; rs++){
      int m = wid*48 + mf*16 + grp + rs*8;     // query 0..383
      int hl = m >> 3, w = m & 7;
      const float* qr = q + bbase + (size_t)(hl*WWD + wb0 + w)*CC + c0;
      float2 qa = *(const float2*)(qr + 2*tig);
      float2 qb = *(const float2*)(qr + 2*tig + 8);
      aq[mf][rs]   = cvt_h2(qa.x*SCL, qa.y*SCL);
      aq[mf][rs+2] = cvt_h2(qb.x*SCL, qb.y*SCL);
    }
  }
  __syncthreads();

  float o[3][2][4];
  #pragma unroll
  for (int mf = 0; mf < 3; mf++)
    #pragma unroll
    for (int cn = 0; cn < 2; cn++)
      #pragma unroll
      for (int r = 0; r < 4; r++) o[mf][cn][r] = 0.f;
  float lsd[3][4];
  #pragma unroll
  for (int mf = 0; mf < 3; mf++)
    #pragma unroll
    for (int r = 0; r < 4; r++) lsd[mf][r] = 0.f;

  const u32 zc = 0u;

  // ---- warp-skewed mainloop over the 24-step key ring ----
  int tcur = wid*3;
  #pragma unroll 4
  for (int it = 0; it < 24; it++){
    const int t_ = tcur;
    tcur = (tcur + 1 < 24) ? tcur + 1 : 0;
    const int lbase = t_*512 + grp*64 + tig*16;
    uint4 kk = *(const uint4*)(sK + lbase);
    uint4 vk = *(const uint4*)(sV + lbase);
    #pragma unroll
    for (int mf = 0; mf < 3; mf++){
      u32 d00, d01, d10, d11;
      mma_f16h(d00, d01, aq[mf], kk.x, kk.y, zc);
      mma_f16h(d10, d11, aq[mf], kk.z, kk.w, zc);
      u32 pa[4];
      pa[0] = ex2h2(d00);
      pa[1] = ex2h2(d01);
      pa[2] = ex2h2(d10);
      pa[3] = ex2h2(d11);
      mma_f16(o[mf][0], pa, vk.x, vk.y);
      mma_f16(o[mf][1], pa, vk.z, vk.w);
      mma_f16(lsd[mf], pa, ONES16, ONES16);   // every col = row-sum of P
    }
  }

  // ---- epilogue: HFMA2 conv + bias + normalize + store ----
  #pragma unroll
  for (int mf = 0; mf < 3; mf++){
    float rinv0 = 1.0f / lsd[mf][0];     // row grp
    float rinv1 = 1.0f / lsd[mf][2];     // row grp+8
    #pragma unroll
    for (int rs = 0; rs < 2; rs++){
      int m = wid*48 + mf*16 + grp + rs*8;
      int hl = m >> 3, w = m & 7;
      float rinv = rs ? rinv1 : rinv0;
      float* orow = out + bbase + (size_t)(hl*WWD + wb0 + w)*CC + c0;
      #pragma unroll
      for (int cn = 0; cn < 2; cn++){
        int cp = cn*4 + tig;     // channel pair index
        __half2 acc = sB2[cp];
        #pragma unroll
        for (int t = 0; t < 9; t++){
          int dy = t/3, dx = t - dy*3;
          acc = __hfma2(sW2[t*8+cp], haloh[((hl+dy)*10 + (w+dx))*8 + cp], acc);
        }
        float2 cv = __half22float2(acc);
        float2 res;
        res.x = o[mf][cn][rs*2]   * rinv + cv.x;
        res.y = o[mf][cn][rs*2+1] * rinv + cv.y;
        *(float2*)(orow + cn*8 + 2*tig) = res;
      }
    }
  }
}

// ---------------------------------------------------------------------------
extern "C" void kernel_launch(void* const* d_in, const int* in_sizes, int n_in,
                              void* d_out, int out_size){
  const float* q    = (const float*)d_in[0];
  const float* k    = (const float*)d_in[1];
  const float* v    = (const float*)d_in[2];
  const float* p1w  = (const float*)d_in[3];
  const float* p1b  = (const float*)d_in[4];
  const float* bng  = (const float*)d_in[5];
  const float* bnb  = (const float*)d_in[6];
  const float* bnm  = (const float*)d_in[7];
  const float* bnv  = (const float*)d_in[8];
  const float* p2w  = (const float*)d_in[9];
  const float* p2b  = (const float*)d_in[10];
  const float* dynw = (const float*)d_in[11];
  const float* dynb = (const float*)d_in[12];
  float* out = (float*)d_out;

  cudaFuncSetAttribute(attn_kernel, cudaFuncAttributeMaxDynamicSharedMemorySize, SMEM_SZ);

  pool_kernel<<<dim3(9, BB, 2), 512>>>(v);
  proj_kernel<<<dim3(BB, 10), 128>>>(p1w, p1b, bng, bnb, bnm, bnv, p2w, p2b, dynw, dynb);
  attn_kernel<<<dim3(NHH, NWIN, BB), 256, SMEM_SZ>>>(q, k, v, out);
}